// round 12
// baseline (speedup 1.0000x reference)
#include <cuda_runtime.h>
#include <cuda_bf16.h>
#include <cstdint>
#include <float.h>
#include <math.h>

#define BATCH 4
#define HW    4096
#define CDIM  256
#define NSTRIP 32
#define NPAIR  528
#define EPSQ  1e-9f
#define TLC   0.6f
#define LC    2.0f
#define MARGIN 0.75f
#define SROWB 144                 // bf16 staging row stride (128B data + 16B pad)
#define TENB  (128 * SROWB)
#define STAGEB (2 * TENB)
#define TOTSMEM (2 * STAGEB)      // 73728 B per CTA (Dt 64KB aliases this)
#define DPW   128                 // D-tile words per row (XOR-swizzled blocks)

// static device scratch
__device__ __nv_bfloat16 g_xhi[BATCH * HW * CDIM];
__device__ float    g_norms[BATCH * HW];
__device__ uint32_t g_pc[(size_t)BATCH * HW * NSTRIP * 4];  // packed (val25|idx7)
__device__ int      g_flagcnt;
__device__ int      g_flaglist[BATCH * HW];

// ---------------------------------------------------------------------------
__device__ __forceinline__ uint32_t smem_u32(const void* p) {
    uint32_t a;
    asm("{ .reg .u64 t; cvta.to.shared.u64 t, %1; cvt.u32.u64 %0, t; }"
        : "=r"(a) : "l"(p));
    return a;
}
__device__ __forceinline__ void cp16(uint32_t dst, const void* src) {
    asm volatile("cp.async.cg.shared.global [%0], [%1], 16;" :: "r"(dst), "l"(src));
}
__device__ __forceinline__ void cp_commit() {
    asm volatile("cp.async.commit_group;" ::: "memory");
}
template <int N> __device__ __forceinline__ void cp_wait() {
    asm volatile("cp.async.wait_group %0;" :: "n"(N) : "memory");
}
__device__ __forceinline__ void ldsm_x4(uint32_t (&r)[4], uint32_t addr) {
    asm volatile("ldmatrix.sync.aligned.m8n8.x4.shared.b16 {%0,%1,%2,%3}, [%4];"
                 : "=r"(r[0]), "=r"(r[1]), "=r"(r[2]), "=r"(r[3]) : "r"(addr));
}
__device__ __forceinline__ uint32_t redux_min_u32(uint32_t v) {
    uint32_t r;
    asm volatile("redux.sync.min.u32 %0, %1, 0xffffffff;" : "=r"(r) : "r"(v));
    return r;
}
#define MMA16816(d, a, b0_, b1_)                                                 \
    asm volatile("mma.sync.aligned.m16n8k16.row.col.f32.bf16.bf16.f32 "          \
                 "{%0,%1,%2,%3}, {%4,%5,%6,%7}, {%8,%9}, {%0,%1,%2,%3};"         \
                 : "+f"((d)[0]), "+f"((d)[1]), "+f"((d)[2]), "+f"((d)[3])        \
                 : "r"((a)[0]), "r"((a)[1]), "r"((a)[2]), "r"((a)[3]),           \
                   "r"(b0_), "r"(b1_))

// swizzled D-tile word index for logical (row r, col c)
__device__ __forceinline__ int dsw(int r, int c) {
    return r * DPW + ((((c >> 2) ^ (r & 31)) << 2) | (c & 3));
}
__device__ __forceinline__ bool ltp(float av, int ai, float bv, int bi) {
    return (av < bv) || (av == bv && ai < bi);
}
// ascending compare-exchange on packed keys (2 instr: min + max)
__device__ __forceinline__ void ceu(uint32_t& a, uint32_t& b) {
    uint32_t mn = min(a, b);
    b = max(a, b);
    a = mn;
}
__device__ __forceinline__ void sort4u(uint32_t (&k)[4]) {
    ceu(k[0], k[1]); ceu(k[2], k[3]);
    ceu(k[0], k[2]); ceu(k[1], k[3]);
    ceu(k[1], k[2]);
}
__device__ __forceinline__ float predict(float m1, float m2) {
    float d1 = sqrtf(fmaxf(m1, 0.f) + EPSQ);
    float d2 = sqrtf(fmaxf(m2, 0.f) + EPSQ);
    float e  = expf(d1);
    return (d1 / d2 < TLC) ? 2.f / (1.f + e) : 2.f / (1.f + LC * e);
}

// ---------------------------------------------------------------------------
// Kernel 1: fused bf16 convert + fp32 row norms (one warp per row)
// ---------------------------------------------------------------------------
__global__ void convert_norms_kernel(const float* __restrict__ x) {
    if (blockIdx.x == 0 && threadIdx.x == 0) g_flagcnt = 0;
    int gw   = (blockIdx.x * blockDim.x + threadIdx.x) >> 5;
    int lane = threadIdx.x & 31;
    if (gw >= BATCH * HW) return;
    const float* xr = x + (size_t)gw * CDIM + lane * 8;
    float4 v0 = *(const float4*)xr;
    float4 v1 = *(const float4*)(xr + 4);
    float s = v0.x*v0.x + v0.y*v0.y + v0.z*v0.z + v0.w*v0.w
            + v1.x*v1.x + v1.y*v1.y + v1.z*v1.z + v1.w*v1.w;
    __nv_bfloat162 p0(__float2bfloat16(v0.x), __float2bfloat16(v0.y));
    __nv_bfloat162 p1(__float2bfloat16(v0.z), __float2bfloat16(v0.w));
    __nv_bfloat162 p2(__float2bfloat16(v1.x), __float2bfloat16(v1.y));
    __nv_bfloat162 p3(__float2bfloat16(v1.z), __float2bfloat16(v1.w));
    uint4 u;
    u.x = *(uint32_t*)&p0; u.y = *(uint32_t*)&p1;
    u.z = *(uint32_t*)&p2; u.w = *(uint32_t*)&p3;
    ((uint4*)g_xhi)[(size_t)gw * 32 + lane] = u;
    #pragma unroll
    for (int o = 16; o; o >>= 1) s += __shfl_xor_sync(0xffffffffu, s, o);
    if (lane == 0) g_norms[gw] = s;
}

// ---------------------------------------------------------------------------
// Kernel 2: single-pass bf16 Gram tile-pair + packed-key top-4 per row/col.
// Occupancy 2; extraction with 4-task redux ILP.
// ---------------------------------------------------------------------------
__global__ __launch_bounds__(512, 2)
void fcm_pair_kernel() {
    extern __shared__ __align__(16) char smem[];
    const uint32_t sbase = smem_u32(smem);

    const int tid  = threadIdx.x;
    const int lane = tid & 31;
    const int w    = tid >> 5;
    const int mw   = w >> 2;
    const int nw   = w & 3;
    const int b    = blockIdx.y;

    int p = blockIdx.x;
    int i = (int)((65.0f - sqrtf(4225.0f - 8.0f * (float)p)) * 0.5f);
    while ((i + 1) * (65 - (i + 1)) / 2 <= p) ++i;
    while (i * (65 - i) / 2 > p) --i;
    const int j = i + (p - i * (65 - i) / 2);
    const int row0 = i * 128, col0 = j * 128;
    const bool diag = (i == j);

    const __nv_bfloat16* xb = g_xhi + (size_t)b * HW * CDIM;
    const int lrow = ((lane >> 3) & 1) * 8 + (lane & 7);
    const int lkb  = (lane >> 4) * 16;

    auto stage = [&](int kc) {
        const uint32_t dst = sbase + (uint32_t)((kc & 1) * STAGEB);
        #pragma unroll
        for (int o = 0; o < 2; ++o) {
            int lin = tid + o * 512;
            int r = lin >> 3, gg = lin & 7;
            cp16(dst + (uint32_t)(r * SROWB + gg * 16),
                 xb + (size_t)(row0 + r) * CDIM + kc * 64 + gg * 8);
            cp16(dst + TENB + (uint32_t)(r * SROWB + gg * 16),
                 xb + (size_t)(col0 + r) * CDIM + kc * 64 + gg * 8);
        }
        cp_commit();
    };
    stage(0);

    float acc[2][4][4];
    #pragma unroll
    for (int mf = 0; mf < 2; ++mf)
        #pragma unroll
        for (int nf = 0; nf < 4; ++nf)
            #pragma unroll
            for (int e = 0; e < 4; ++e) acc[mf][nf][e] = 0.f;

    for (int kc = 0; kc < 4; ++kc) {
        cp_wait<0>();
        __syncthreads();
        if (kc < 3) stage(kc + 1);
        const uint32_t bb  = sbase + (uint32_t)((kc & 1) * STAGEB);
        const uint32_t ab  = bb + (uint32_t)((mw * 32 + lrow) * SROWB);
        const uint32_t bbs = bb + TENB + (uint32_t)((nw * 32 + lrow) * SROWB);
        #pragma unroll
        for (int ks = 0; ks < 4; ++ks) {
            const uint32_t kb = (uint32_t)(ks * 32 + lkb);
            uint32_t ah[2][4], bh[2][4];
            ldsm_x4(ah[0], ab + kb);
            ldsm_x4(ah[1], ab + 16 * SROWB + kb);
            ldsm_x4(bh[0], bbs + kb);
            ldsm_x4(bh[1], bbs + 16 * SROWB + kb);
            #pragma unroll
            for (int mf = 0; mf < 2; ++mf)
                #pragma unroll
                for (int nf = 0; nf < 4; ++nf)
                    MMA16816(acc[mf][nf], ah[mf],
                             bh[nf >> 1][nf & 1], bh[nf >> 1][(nf & 1) + 2]);
        }
    }
    __syncthreads();                 // ldsm done; alias smem as swizzled D-tile

    // ---- fp32 squared-distance tile into swizzled SMEM ----
    float* Dt = (float*)smem;
    #pragma unroll
    for (int mf = 0; mf < 2; ++mf) {
        const int r0l = mw * 32 + mf * 16 + (lane >> 2);
        const float na0 = g_norms[b * HW + row0 + r0l];
        const float na1 = g_norms[b * HW + row0 + r0l + 8];
        const float* nbp = g_norms + b * HW + col0 + nw * 32 + (lane & 3) * 2;
        #pragma unroll
        for (int nf = 0; nf < 4; ++nf) {
            float2 nb = *(const float2*)(nbp + nf * 8);
            int cl = nw * 32 + nf * 8 + (lane & 3) * 2;
            float2 d0 = { na0 + nb.x - 2.f * acc[mf][nf][0],
                          na0 + nb.y - 2.f * acc[mf][nf][1] };
            float2 d1 = { na1 + nb.x - 2.f * acc[mf][nf][2],
                          na1 + nb.y - 2.f * acc[mf][nf][3] };
            *(float2*)&Dt[dsw(r0l, cl)]     = d0;
            *(float2*)&Dt[dsw(r0l + 8, cl)] = d1;
        }
    }
    __syncthreads();

    // ---- packed-key top-4 extraction: 4 tasks/iter, 1 redux per pop ----
    const int ntask = diag ? 128 : 256;
    for (int t0 = w; t0 < ntask; t0 += 64) {
        uint32_t k[4][4];
        #pragma unroll
        for (int u = 0; u < 4; ++u) {
            const int t = t0 + 16 * u;
            if (t < 128) {                              // row task: local cols
                const int rr = t;
                const float4 dv =
                    *(const float4*)&Dt[rr * DPW + ((lane ^ (rr & 31)) << 2)];
                k[u][0] = (__float_as_uint(dv.x) & 0xFFFFFF80u) | (lane * 4 + 0);
                k[u][1] = (__float_as_uint(dv.y) & 0xFFFFFF80u) | (lane * 4 + 1);
                k[u][2] = (__float_as_uint(dv.z) & 0xFFFFFF80u) | (lane * 4 + 2);
                k[u][3] = (__float_as_uint(dv.w) & 0xFFFFFF80u) | (lane * 4 + 3);
                if (diag && (rr >> 2) == lane) k[u][rr & 3] = 0xFFFFFFFFu;
            } else {                                    // col task: local rows
                const int cc = t - 128;
                const int cb = cc >> 2, cq = cc & 3;
                #pragma unroll
                for (int q = 0; q < 4; ++q) {
                    const int r = lane + 32 * q;
                    k[u][q] = (__float_as_uint(
                        Dt[r * DPW + (((cb ^ (r & 31)) << 2) | cq)]) & 0xFFFFFF80u)
                        | (uint32_t)r;
                }
            }
            sort4u(k[u]);
        }

        uint32_t myk[4];
        #pragma unroll
        for (int pp = 0; pp < 4; ++pp) {
            uint32_t g[4];
            #pragma unroll
            for (int u = 0; u < 4; ++u) g[u] = redux_min_u32(k[u][0]);
            if (lane == pp) {
                #pragma unroll
                for (int u = 0; u < 4; ++u) myk[u] = g[u];
            }
            #pragma unroll
            for (int u = 0; u < 4; ++u) {
                if (k[u][0] == g[u]) {
                    k[u][0] = k[u][1]; k[u][1] = k[u][2];
                    k[u][2] = k[u][3]; k[u][3] = 0xFFFFFFFFu;
                }
            }
        }
        if (lane < 4) {
            #pragma unroll
            for (int u = 0; u < 4; ++u) {
                const int t = t0 + 16 * u;
                const int grow = (t < 128) ? (row0 + t) : (col0 + (t - 128));
                const int slot = (t < 128) ? j : i;
                g_pc[(((size_t)(b * HW + grow)) * NSTRIP + slot) * 4 + lane] = myk[u];
            }
        }
    }
}

// ---------------------------------------------------------------------------
// Kernel 3: warp-per-row merge (packed-key pop-min over 32 slot lists) +
// exact fp32 refinement of 8 candidates + margin flagging.
// ---------------------------------------------------------------------------
__global__ void merge_refine_kernel(const float* __restrict__ x,
                                    float* __restrict__ out, int out_size) {
    int gw   = (blockIdx.x * blockDim.x + threadIdx.x) >> 5;
    int lane = threadIdx.x & 31;
    if (gw >= BATCH * HW) return;
    const int b = gw >> 12, rl = gw & 4095;

    const uint4 kk = *(const uint4*)(g_pc + ((size_t)gw * NSTRIP + lane) * 4);

    // B1 = min over tiles of the stored 4th-smallest value (lower bound)
    const uint32_t b1 = redux_min_u32(kk.w);

    // repack: 20-bit value | 12-bit global index (slot*128 + idx7); re-sort
    const uint32_t base = (uint32_t)lane * 128u;
    uint32_t mk[4];
    mk[0] = (kk.x & 0xFFFFF000u) | (base + (kk.x & 0x7Fu));
    mk[1] = (kk.y & 0xFFFFF000u) | (base + (kk.y & 0x7Fu));
    mk[2] = (kk.z & 0xFFFFF000u) | (base + (kk.z & 0x7Fu));
    mk[3] = (kk.w & 0xFFFFF000u) | (base + (kk.w & 0x7Fu));
    sort4u(mk);

    uint32_t gks[8];
    #pragma unroll
    for (int pp = 0; pp < 8; ++pp) {
        uint32_t gv = redux_min_u32(mk[0]);
        gks[pp] = gv;
        if (mk[0] == gv) {
            mk[0] = mk[1]; mk[1] = mk[2]; mk[2] = mk[3]; mk[3] = 0xFFFFFFFFu;
        }
    }

    // exact fp32 refinement of the 8 global candidates
    const float* xb = x + (size_t)b * HW * CDIM;
    const float* xr = xb + (size_t)rl * CDIM + lane * 8;
    float4 a0 = *(const float4*)xr;
    float4 a1 = *(const float4*)(xr + 4);
    const float nr = g_norms[b * HW + rl];

    float m1 = FLT_MAX, m2 = FLT_MAX; int j1 = 0, j2 = 0;
    #pragma unroll
    for (int k = 0; k < 8; ++k) {
        const int c = (int)(gks[k] & 0xFFFu);
        const float* xc = xb + (size_t)c * CDIM + lane * 8;
        float4 c0 = *(const float4*)xc;
        float4 c1 = *(const float4*)(xc + 4);
        float s = a0.x*c0.x + a0.y*c0.y + a0.z*c0.z + a0.w*c0.w
                + a1.x*c1.x + a1.y*c1.y + a1.z*c1.z + a1.w*c1.w;
        #pragma unroll
        for (int off = 16; off; off >>= 1) s += __shfl_xor_sync(0xffffffffu, s, off);
        float D = nr + g_norms[b * HW + c] - 2.f * s;
        if (ltp(D, c, m1, j1)) { m2 = m1; j2 = j1; m1 = D; j1 = c; }
        else if (ltp(D, c, m2, j2)) { m2 = D; j2 = c; }
    }

    if (lane == 0) {
        out[(size_t)b * HW + rl] = predict(m1, m2);
        if (out_size >= 2 * BATCH * HW)
            out[(size_t)BATCH * HW + (size_t)b * HW + rl] = (float)j1;
        // bound: stored values are lower bounds of bf16 D; exact >= bound-MARGIN
        float bound = fminf(__uint_as_float(b1 & 0xFFFFFF80u),
                            __uint_as_float(gks[7] & 0xFFFFF000u));
        if (m2 > bound - MARGIN) {
            int fi = atomicAdd(&g_flagcnt, 1);
            g_flaglist[fi] = gw;
        }
    }
}

// ---------------------------------------------------------------------------
// Kernel 4: exact full-row rescan for flagged rows (expected ~0 rows).
// ---------------------------------------------------------------------------
__global__ void fallback_kernel(const float* __restrict__ x,
                                float* __restrict__ out, int out_size) {
    __shared__ float sv1[256], sv2[256];
    __shared__ int   si1[256];
    const int n = g_flagcnt;
    for (int fi = blockIdx.x; fi < n; fi += gridDim.x) {
        const int rowg = g_flaglist[fi];
        const int b = rowg >> 12, r = rowg & 4095;
        const float* xb = x + (size_t)b * HW * CDIM;
        const float* xr = xb + (size_t)r * CDIM;
        const float  nr = g_norms[rowg];
        float v1 = FLT_MAX, v2 = FLT_MAX; int i1 = 0x7fffffff;
        for (int c = threadIdx.x; c < HW; c += 256) {
            if (c == r) continue;
            const float4* xc = (const float4*)(xb + (size_t)c * CDIM);
            float s = 0.f;
            #pragma unroll
            for (int d = 0; d < 64; ++d) {
                float4 va = ((const float4*)xr)[d];
                float4 vb = xc[d];
                s += va.x*vb.x + va.y*vb.y + va.z*vb.z + va.w*vb.w;
            }
            float D = nr + g_norms[b * HW + c] - 2.f * s;
            if (ltp(D, c, v1, i1)) { v2 = v1; v1 = D; i1 = c; }
            else if (D < v2) { v2 = D; }
        }
        sv1[threadIdx.x] = v1; sv2[threadIdx.x] = v2; si1[threadIdx.x] = i1;
        __syncthreads();
        for (int off = 128; off; off >>= 1) {
            if (threadIdx.x < off) {
                float b1 = sv1[threadIdx.x + off], b2 = sv2[threadIdx.x + off];
                int   bi = si1[threadIdx.x + off];
                float a1v = sv1[threadIdx.x]; int a1i = si1[threadIdx.x];
                if (ltp(b1, bi, a1v, a1i)) {
                    sv2[threadIdx.x] = fminf(a1v, b2);
                    sv1[threadIdx.x] = b1; si1[threadIdx.x] = bi;
                } else {
                    sv2[threadIdx.x] = fminf(sv2[threadIdx.x], b1);
                }
            }
            __syncthreads();
        }
        if (threadIdx.x == 0) {
            out[(size_t)b * HW + r] = predict(sv1[0], sv2[0]);
            if (out_size >= 2 * BATCH * HW)
                out[(size_t)BATCH * HW + (size_t)b * HW + r] = (float)si1[0];
        }
        __syncthreads();
    }
}

// ---------------------------------------------------------------------------
extern "C" void kernel_launch(void* const* d_in, const int* in_sizes, int n_in,
                              void* d_out, int out_size) {
    const float* x   = (const float*)d_in[0];
    float*       out = (float*)d_out;

    convert_norms_kernel<<<BATCH * HW / 8, 256>>>(x);

    cudaFuncSetAttribute(fcm_pair_kernel,
                         cudaFuncAttributeMaxDynamicSharedMemorySize, TOTSMEM);
    dim3 grid(NPAIR, BATCH);
    fcm_pair_kernel<<<grid, 512, TOTSMEM>>>();

    merge_refine_kernel<<<BATCH * HW / 8, 256>>>(x, out, out_size);
    fallback_kernel<<<256, 256>>>(x, out, out_size);
}

// round 13
// speedup vs baseline: 1.0879x; 1.0879x over previous
#include <cuda_runtime.h>
#include <cuda_bf16.h>
#include <cstdint>
#include <float.h>
#include <math.h>

#define BATCH 4
#define HW    4096
#define CDIM  256
#define NSTRIP 32
#define NPAIR  528
#define EPSQ  1e-9f
#define TLC   0.6f
#define LC    2.0f
#define MARGIN 0.75f
#define SROWB 144                 // bf16 staging row stride (128B data + 16B pad)
#define TENB  (128 * SROWB)
#define STAGEB (2 * TENB)
#define TOTSMEM (2 * STAGEB)      // 73728 B per CTA (Dt 64KB aliases this)
#define DPW   128                 // D-tile words per row (XOR-swizzled blocks)

// static device scratch
__device__ __nv_bfloat16 g_xhi[BATCH * HW * CDIM];
__device__ float    g_norms[BATCH * HW];
__device__ uint32_t g_pc[(size_t)BATCH * HW * NSTRIP * 4];  // packed (val25|idx7)
__device__ int      g_flagcnt;
__device__ int      g_flaglist[BATCH * HW];

// ---------------------------------------------------------------------------
__device__ __forceinline__ uint32_t smem_u32(const void* p) {
    uint32_t a;
    asm("{ .reg .u64 t; cvta.to.shared.u64 t, %1; cvt.u32.u64 %0, t; }"
        : "=r"(a) : "l"(p));
    return a;
}
__device__ __forceinline__ void cp16(uint32_t dst, const void* src) {
    asm volatile("cp.async.cg.shared.global [%0], [%1], 16;" :: "r"(dst), "l"(src));
}
__device__ __forceinline__ void cp_commit() {
    asm volatile("cp.async.commit_group;" ::: "memory");
}
template <int N> __device__ __forceinline__ void cp_wait() {
    asm volatile("cp.async.wait_group %0;" :: "n"(N) : "memory");
}
__device__ __forceinline__ void ldsm_x4(uint32_t (&r)[4], uint32_t addr) {
    asm volatile("ldmatrix.sync.aligned.m8n8.x4.shared.b16 {%0,%1,%2,%3}, [%4];"
                 : "=r"(r[0]), "=r"(r[1]), "=r"(r[2]), "=r"(r[3]) : "r"(addr));
}
__device__ __forceinline__ uint32_t redux_min_u32(uint32_t v) {
    uint32_t r;
    asm volatile("redux.sync.min.u32 %0, %1, 0xffffffff;" : "=r"(r) : "r"(v));
    return r;
}
#define MMA16816(d, a, b0_, b1_)                                                 \
    asm volatile("mma.sync.aligned.m16n8k16.row.col.f32.bf16.bf16.f32 "          \
                 "{%0,%1,%2,%3}, {%4,%5,%6,%7}, {%8,%9}, {%0,%1,%2,%3};"         \
                 : "+f"((d)[0]), "+f"((d)[1]), "+f"((d)[2]), "+f"((d)[3])        \
                 : "r"((a)[0]), "r"((a)[1]), "r"((a)[2]), "r"((a)[3]),           \
                   "r"(b0_), "r"(b1_))

// swizzled D-tile word index for logical (row r, col c)
__device__ __forceinline__ int dsw(int r, int c) {
    return r * DPW + ((((c >> 2) ^ (r & 31)) << 2) | (c & 3));
}
__device__ __forceinline__ bool ltp(float av, int ai, float bv, int bi) {
    return (av < bv) || (av == bv && ai < bi);
}
// ascending compare-exchange on packed keys (2 instr: min + max)
__device__ __forceinline__ void ceu(uint32_t& a, uint32_t& b) {
    uint32_t mn = min(a, b);
    b = max(a, b);
    a = mn;
}
__device__ __forceinline__ void sort4u(uint32_t (&k)[4]) {
    ceu(k[0], k[1]); ceu(k[2], k[3]);
    ceu(k[0], k[2]); ceu(k[1], k[3]);
    ceu(k[1], k[2]);
}
__device__ __forceinline__ float predict(float m1, float m2) {
    float d1 = sqrtf(fmaxf(m1, 0.f) + EPSQ);
    float d2 = sqrtf(fmaxf(m2, 0.f) + EPSQ);
    float e  = expf(d1);
    return (d1 / d2 < TLC) ? 2.f / (1.f + e) : 2.f / (1.f + LC * e);
}

// ---------------------------------------------------------------------------
// Kernel 1: fused bf16 convert + fp32 row norms (two rows per warp, 4
// independent float4 loads per lane for MLP; two interleaved reductions)
// ---------------------------------------------------------------------------
__global__ void convert_norms_kernel(const float* __restrict__ x) {
    if (blockIdx.x == 0 && threadIdx.x == 0) g_flagcnt = 0;
    int warp = (blockIdx.x * blockDim.x + threadIdx.x) >> 5;  // 0..8191
    int lane = threadIdx.x & 31;
    int r0 = warp * 2;                                        // rows r0, r0+1
    const float* xr0 = x + (size_t)r0 * CDIM + lane * 8;
    const float* xr1 = xr0 + CDIM;
    float4 a0 = *(const float4*)xr0;
    float4 a1 = *(const float4*)(xr0 + 4);
    float4 b0 = *(const float4*)xr1;
    float4 b1 = *(const float4*)(xr1 + 4);

    float sa = a0.x*a0.x + a0.y*a0.y + a0.z*a0.z + a0.w*a0.w
             + a1.x*a1.x + a1.y*a1.y + a1.z*a1.z + a1.w*a1.w;
    float sb = b0.x*b0.x + b0.y*b0.y + b0.z*b0.z + b0.w*b0.w
             + b1.x*b1.x + b1.y*b1.y + b1.z*b1.z + b1.w*b1.w;

    __nv_bfloat162 p0(__float2bfloat16(a0.x), __float2bfloat16(a0.y));
    __nv_bfloat162 p1(__float2bfloat16(a0.z), __float2bfloat16(a0.w));
    __nv_bfloat162 p2(__float2bfloat16(a1.x), __float2bfloat16(a1.y));
    __nv_bfloat162 p3(__float2bfloat16(a1.z), __float2bfloat16(a1.w));
    uint4 u;
    u.x = *(uint32_t*)&p0; u.y = *(uint32_t*)&p1;
    u.z = *(uint32_t*)&p2; u.w = *(uint32_t*)&p3;
    ((uint4*)g_xhi)[(size_t)r0 * 32 + lane] = u;
    __nv_bfloat162 q0(__float2bfloat16(b0.x), __float2bfloat16(b0.y));
    __nv_bfloat162 q1(__float2bfloat16(b0.z), __float2bfloat16(b0.w));
    __nv_bfloat162 q2(__float2bfloat16(b1.x), __float2bfloat16(b1.y));
    __nv_bfloat162 q3(__float2bfloat16(b1.z), __float2bfloat16(b1.w));
    u.x = *(uint32_t*)&q0; u.y = *(uint32_t*)&q1;
    u.z = *(uint32_t*)&q2; u.w = *(uint32_t*)&q3;
    ((uint4*)g_xhi)[(size_t)(r0 + 1) * 32 + lane] = u;

    #pragma unroll
    for (int o = 16; o; o >>= 1) {
        sa += __shfl_xor_sync(0xffffffffu, sa, o);
        sb += __shfl_xor_sync(0xffffffffu, sb, o);
    }
    if (lane == 0) { g_norms[r0] = sa; g_norms[r0 + 1] = sb; }
}

// ---------------------------------------------------------------------------
// Kernel 2: single-pass bf16 Gram tile-pair + packed-key top-4 per row/col.
// Occupancy 2; extraction with 2-task redux ILP.  (R10 configuration.)
// ---------------------------------------------------------------------------
__global__ __launch_bounds__(512, 2)
void fcm_pair_kernel() {
    extern __shared__ __align__(16) char smem[];
    const uint32_t sbase = smem_u32(smem);

    const int tid  = threadIdx.x;
    const int lane = tid & 31;
    const int w    = tid >> 5;
    const int mw   = w >> 2;
    const int nw   = w & 3;
    const int b    = blockIdx.y;

    int p = blockIdx.x;
    int i = (int)((65.0f - sqrtf(4225.0f - 8.0f * (float)p)) * 0.5f);
    while ((i + 1) * (65 - (i + 1)) / 2 <= p) ++i;
    while (i * (65 - i) / 2 > p) --i;
    const int j = i + (p - i * (65 - i) / 2);
    const int row0 = i * 128, col0 = j * 128;
    const bool diag = (i == j);

    const __nv_bfloat16* xb = g_xhi + (size_t)b * HW * CDIM;
    const int lrow = ((lane >> 3) & 1) * 8 + (lane & 7);
    const int lkb  = (lane >> 4) * 16;

    auto stage = [&](int kc) {
        const uint32_t dst = sbase + (uint32_t)((kc & 1) * STAGEB);
        #pragma unroll
        for (int o = 0; o < 2; ++o) {
            int lin = tid + o * 512;
            int r = lin >> 3, gg = lin & 7;
            cp16(dst + (uint32_t)(r * SROWB + gg * 16),
                 xb + (size_t)(row0 + r) * CDIM + kc * 64 + gg * 8);
            cp16(dst + TENB + (uint32_t)(r * SROWB + gg * 16),
                 xb + (size_t)(col0 + r) * CDIM + kc * 64 + gg * 8);
        }
        cp_commit();
    };
    stage(0);

    float acc[2][4][4];
    #pragma unroll
    for (int mf = 0; mf < 2; ++mf)
        #pragma unroll
        for (int nf = 0; nf < 4; ++nf)
            #pragma unroll
            for (int e = 0; e < 4; ++e) acc[mf][nf][e] = 0.f;

    for (int kc = 0; kc < 4; ++kc) {
        cp_wait<0>();
        __syncthreads();
        if (kc < 3) stage(kc + 1);
        const uint32_t bb  = sbase + (uint32_t)((kc & 1) * STAGEB);
        const uint32_t ab  = bb + (uint32_t)((mw * 32 + lrow) * SROWB);
        const uint32_t bbs = bb + TENB + (uint32_t)((nw * 32 + lrow) * SROWB);
        #pragma unroll
        for (int ks = 0; ks < 4; ++ks) {
            const uint32_t kb = (uint32_t)(ks * 32 + lkb);
            uint32_t ah[2][4], bh[2][4];
            ldsm_x4(ah[0], ab + kb);
            ldsm_x4(ah[1], ab + 16 * SROWB + kb);
            ldsm_x4(bh[0], bbs + kb);
            ldsm_x4(bh[1], bbs + 16 * SROWB + kb);
            #pragma unroll
            for (int mf = 0; mf < 2; ++mf)
                #pragma unroll
                for (int nf = 0; nf < 4; ++nf)
                    MMA16816(acc[mf][nf], ah[mf],
                             bh[nf >> 1][nf & 1], bh[nf >> 1][(nf & 1) + 2]);
        }
    }
    __syncthreads();                 // ldsm done; alias smem as swizzled D-tile

    // ---- fp32 squared-distance tile into swizzled SMEM ----
    float* Dt = (float*)smem;
    #pragma unroll
    for (int mf = 0; mf < 2; ++mf) {
        const int r0l = mw * 32 + mf * 16 + (lane >> 2);
        const float na0 = g_norms[b * HW + row0 + r0l];
        const float na1 = g_norms[b * HW + row0 + r0l + 8];
        const float* nbp = g_norms + b * HW + col0 + nw * 32 + (lane & 3) * 2;
        #pragma unroll
        for (int nf = 0; nf < 4; ++nf) {
            float2 nb = *(const float2*)(nbp + nf * 8);
            int cl = nw * 32 + nf * 8 + (lane & 3) * 2;
            float2 d0 = { na0 + nb.x - 2.f * acc[mf][nf][0],
                          na0 + nb.y - 2.f * acc[mf][nf][1] };
            float2 d1 = { na1 + nb.x - 2.f * acc[mf][nf][2],
                          na1 + nb.y - 2.f * acc[mf][nf][3] };
            *(float2*)&Dt[dsw(r0l, cl)]     = d0;
            *(float2*)&Dt[dsw(r0l + 8, cl)] = d1;
        }
    }
    __syncthreads();

    // ---- packed-key top-4 extraction: 2 tasks/iter, 1 redux per pop ----
    const int ntask = diag ? 128 : 256;
    for (int t0 = w; t0 < ntask; t0 += 32) {
        uint32_t k[2][4];
        #pragma unroll
        for (int u = 0; u < 2; ++u) {
            const int t = t0 + 16 * u;
            if (t < 128) {                              // row task: local cols
                const int rr = t;
                const float4 dv =
                    *(const float4*)&Dt[rr * DPW + ((lane ^ (rr & 31)) << 2)];
                k[u][0] = (__float_as_uint(dv.x) & 0xFFFFFF80u) | (lane * 4 + 0);
                k[u][1] = (__float_as_uint(dv.y) & 0xFFFFFF80u) | (lane * 4 + 1);
                k[u][2] = (__float_as_uint(dv.z) & 0xFFFFFF80u) | (lane * 4 + 2);
                k[u][3] = (__float_as_uint(dv.w) & 0xFFFFFF80u) | (lane * 4 + 3);
                if (diag && (rr >> 2) == lane) k[u][rr & 3] = 0xFFFFFFFFu;
            } else {                                    // col task: local rows
                const int cc = t - 128;
                const int cb = cc >> 2, cq = cc & 3;
                #pragma unroll
                for (int q = 0; q < 4; ++q) {
                    const int r = lane + 32 * q;
                    k[u][q] = (__float_as_uint(
                        Dt[r * DPW + (((cb ^ (r & 31)) << 2) | cq)]) & 0xFFFFFF80u)
                        | (uint32_t)r;
                }
            }
            sort4u(k[u]);
        }

        uint32_t myk[2];
        #pragma unroll
        for (int pp = 0; pp < 4; ++pp) {
            uint32_t g0 = redux_min_u32(k[0][0]);
            uint32_t g1 = redux_min_u32(k[1][0]);
            if (lane == pp) { myk[0] = g0; myk[1] = g1; }
            if (k[0][0] == g0) {
                k[0][0] = k[0][1]; k[0][1] = k[0][2];
                k[0][2] = k[0][3]; k[0][3] = 0xFFFFFFFFu;
            }
            if (k[1][0] == g1) {
                k[1][0] = k[1][1]; k[1][1] = k[1][2];
                k[1][2] = k[1][3]; k[1][3] = 0xFFFFFFFFu;
            }
        }
        if (lane < 4) {
            #pragma unroll
            for (int u = 0; u < 2; ++u) {
                const int t = t0 + 16 * u;
                const int grow = (t < 128) ? (row0 + t) : (col0 + (t - 128));
                const int slot = (t < 128) ? j : i;
                g_pc[(((size_t)(b * HW + grow)) * NSTRIP + slot) * 4 + lane] = myk[u];
            }
        }
    }
}

// ---------------------------------------------------------------------------
// Kernel 3: warp-per-row merge (packed-key pop-min over 32 slot lists) +
// exact fp32 refinement of 8 candidates (batched shfl reduction) + flagging.
// ---------------------------------------------------------------------------
__global__ void merge_refine_kernel(const float* __restrict__ x,
                                    float* __restrict__ out, int out_size) {
    int gw   = (blockIdx.x * blockDim.x + threadIdx.x) >> 5;
    int lane = threadIdx.x & 31;
    if (gw >= BATCH * HW) return;
    const int b = gw >> 12, rl = gw & 4095;

    const uint4 kk = *(const uint4*)(g_pc + ((size_t)gw * NSTRIP + lane) * 4);

    // B1 = min over tiles of the stored 4th-smallest value (lower bound)
    const uint32_t b1 = redux_min_u32(kk.w);

    // repack: 20-bit value | 12-bit global index (slot*128 + idx7); re-sort
    const uint32_t base = (uint32_t)lane * 128u;
    uint32_t mk[4];
    mk[0] = (kk.x & 0xFFFFF000u) | (base + (kk.x & 0x7Fu));
    mk[1] = (kk.y & 0xFFFFF000u) | (base + (kk.y & 0x7Fu));
    mk[2] = (kk.z & 0xFFFFF000u) | (base + (kk.z & 0x7Fu));
    mk[3] = (kk.w & 0xFFFFF000u) | (base + (kk.w & 0x7Fu));
    sort4u(mk);

    uint32_t gks[8];
    #pragma unroll
    for (int pp = 0; pp < 8; ++pp) {
        uint32_t gv = redux_min_u32(mk[0]);
        gks[pp] = gv;
        if (mk[0] == gv) {
            mk[0] = mk[1]; mk[1] = mk[2]; mk[2] = mk[3]; mk[3] = 0xFFFFFFFFu;
        }
    }

    // exact fp32 refinement: batched partial sums, one interleaved reduction
    const float* xb = x + (size_t)b * HW * CDIM;
    const float* xr = xb + (size_t)rl * CDIM + lane * 8;
    float4 a0 = *(const float4*)xr;
    float4 a1 = *(const float4*)(xr + 4);
    const float nr = g_norms[b * HW + rl];

    float s[8];
    #pragma unroll
    for (int k = 0; k < 8; ++k) {
        const int c = (int)(gks[k] & 0xFFFu);
        const float* xc = xb + (size_t)c * CDIM + lane * 8;
        float4 c0 = *(const float4*)xc;
        float4 c1 = *(const float4*)(xc + 4);
        s[k] = a0.x*c0.x + a0.y*c0.y + a0.z*c0.z + a0.w*c0.w
             + a1.x*c1.x + a1.y*c1.y + a1.z*c1.z + a1.w*c1.w;
    }
    #pragma unroll
    for (int off = 16; off; off >>= 1) {
        #pragma unroll
        for (int k = 0; k < 8; ++k)
            s[k] += __shfl_xor_sync(0xffffffffu, s[k], off);
    }

    float m1 = FLT_MAX, m2 = FLT_MAX; int j1 = 0, j2 = 0;
    #pragma unroll
    for (int k = 0; k < 8; ++k) {
        const int c = (int)(gks[k] & 0xFFFu);
        float D = nr + g_norms[b * HW + c] - 2.f * s[k];
        if (ltp(D, c, m1, j1)) { m2 = m1; j2 = j1; m1 = D; j1 = c; }
        else if (ltp(D, c, m2, j2)) { m2 = D; j2 = c; }
    }

    if (lane == 0) {
        out[(size_t)b * HW + rl] = predict(m1, m2);
        if (out_size >= 2 * BATCH * HW)
            out[(size_t)BATCH * HW + (size_t)b * HW + rl] = (float)j1;
        // bound: stored values are lower bounds of bf16 D; exact >= bound-MARGIN
        float bound = fminf(__uint_as_float(b1 & 0xFFFFFF80u),
                            __uint_as_float(gks[7] & 0xFFFFF000u));
        if (m2 > bound - MARGIN) {
            int fi = atomicAdd(&g_flagcnt, 1);
            g_flaglist[fi] = gw;
        }
    }
}

// ---------------------------------------------------------------------------
// Kernel 4: exact full-row rescan for flagged rows (expected ~0 rows).
// ---------------------------------------------------------------------------
__global__ void fallback_kernel(const float* __restrict__ x,
                                float* __restrict__ out, int out_size) {
    __shared__ float sv1[256], sv2[256];
    __shared__ int   si1[256];
    const int n = g_flagcnt;
    for (int fi = blockIdx.x; fi < n; fi += gridDim.x) {
        const int rowg = g_flaglist[fi];
        const int b = rowg >> 12, r = rowg & 4095;
        const float* xb = x + (size_t)b * HW * CDIM;
        const float* xr = xb + (size_t)r * CDIM;
        const float  nr = g_norms[rowg];
        float v1 = FLT_MAX, v2 = FLT_MAX; int i1 = 0x7fffffff;
        for (int c = threadIdx.x; c < HW; c += 256) {
            if (c == r) continue;
            const float4* xc = (const float4*)(xb + (size_t)c * CDIM);
            float s = 0.f;
            #pragma unroll
            for (int d = 0; d < 64; ++d) {
                float4 va = ((const float4*)xr)[d];
                float4 vb = xc[d];
                s += va.x*vb.x + va.y*vb.y + va.z*vb.z + va.w*vb.w;
            }
            float D = nr + g_norms[b * HW + c] - 2.f * s;
            if (ltp(D, c, v1, i1)) { v2 = v1; v1 = D; i1 = c; }
            else if (D < v2) { v2 = D; }
        }
        sv1[threadIdx.x] = v1; sv2[threadIdx.x] = v2; si1[threadIdx.x] = i1;
        __syncthreads();
        for (int off = 128; off; off >>= 1) {
            if (threadIdx.x < off) {
                float b1 = sv1[threadIdx.x + off], b2 = sv2[threadIdx.x + off];
                int   bi = si1[threadIdx.x + off];
                float a1v = sv1[threadIdx.x]; int a1i = si1[threadIdx.x];
                if (ltp(b1, bi, a1v, a1i)) {
                    sv2[threadIdx.x] = fminf(a1v, b2);
                    sv1[threadIdx.x] = b1; si1[threadIdx.x] = bi;
                } else {
                    sv2[threadIdx.x] = fminf(sv2[threadIdx.x], b1);
                }
            }
            __syncthreads();
        }
        if (threadIdx.x == 0) {
            out[(size_t)b * HW + r] = predict(sv1[0], sv2[0]);
            if (out_size >= 2 * BATCH * HW)
                out[(size_t)BATCH * HW + (size_t)b * HW + r] = (float)si1[0];
        }
        __syncthreads();
    }
}

// ---------------------------------------------------------------------------
extern "C" void kernel_launch(void* const* d_in, const int* in_sizes, int n_in,
                              void* d_out, int out_size) {
    const float* x   = (const float*)d_in[0];
    float*       out = (float*)d_out;

    convert_norms_kernel<<<BATCH * HW / 16, 256>>>(x);

    cudaFuncSetAttribute(fcm_pair_kernel,
                         cudaFuncAttributeMaxDynamicSharedMemorySize, TOTSMEM);
    dim3 grid(NPAIR, BATCH);
    fcm_pair_kernel<<<grid, 512, TOTSMEM>>>();

    merge_refine_kernel<<<BATCH * HW / 8, 256>>>(x, out, out_size);
    fallback_kernel<<<256, 256>>>(x, out, out_size);
}

// round 14
// speedup vs baseline: 1.3108x; 1.2049x over previous
#include <cuda_runtime.h>
#include <cuda_bf16.h>
#include <cstdint>
#include <float.h>
#include <math.h>

#define BATCH 4
#define HW    4096
#define CDIM  256
#define NSTRIP 32
#define NPAIR  528
#define EPSQ  1e-9f
#define TLC   0.6f
#define LC    2.0f
#define MARGIN 0.75f
#define VMASK 0xFFFFC000u         // 18-bit value field (low 14 bits = row|col)
#define SROWB 144                 // bf16 staging row stride (128B data + 16B pad)
#define TENB  (128 * SROWB)
#define STAGEB (2 * TENB)
#define TOTSMEM (2 * STAGEB)      // 73728 B per CTA (Dt 64KB aliases this)
#define DPW   128                 // D-tile words per row (XOR-swizzled blocks)

// static device scratch
__device__ __nv_bfloat16 g_xhi[BATCH * HW * CDIM];
__device__ float    g_norms[BATCH * HW];
__device__ uint32_t g_pc[(size_t)BATCH * HW * NSTRIP * 4];  // packed (val18|..|idx7)
__device__ int      g_flagcnt;
__device__ int      g_flaglist[BATCH * HW];

// ---------------------------------------------------------------------------
__device__ __forceinline__ uint32_t smem_u32(const void* p) {
    uint32_t a;
    asm("{ .reg .u64 t; cvta.to.shared.u64 t, %1; cvt.u32.u64 %0, t; }"
        : "=r"(a) : "l"(p));
    return a;
}
__device__ __forceinline__ void cp16(uint32_t dst, const void* src) {
    asm volatile("cp.async.cg.shared.global [%0], [%1], 16;" :: "r"(dst), "l"(src));
}
__device__ __forceinline__ void cp_commit() {
    asm volatile("cp.async.commit_group;" ::: "memory");
}
template <int N> __device__ __forceinline__ void cp_wait() {
    asm volatile("cp.async.wait_group %0;" :: "n"(N) : "memory");
}
__device__ __forceinline__ void ldsm_x4(uint32_t (&r)[4], uint32_t addr) {
    asm volatile("ldmatrix.sync.aligned.m8n8.x4.shared.b16 {%0,%1,%2,%3}, [%4];"
                 : "=r"(r[0]), "=r"(r[1]), "=r"(r[2]), "=r"(r[3]) : "r"(addr));
}
__device__ __forceinline__ uint32_t redux_min_u32(uint32_t v) {
    uint32_t r;
    asm volatile("redux.sync.min.u32 %0, %1, 0xffffffff;" : "=r"(r) : "r"(v));
    return r;
}
#define MMA16816(d, a, b0_, b1_)                                                 \
    asm volatile("mma.sync.aligned.m16n8k16.row.col.f32.bf16.bf16.f32 "          \
                 "{%0,%1,%2,%3}, {%4,%5,%6,%7}, {%8,%9}, {%0,%1,%2,%3};"         \
                 : "+f"((d)[0]), "+f"((d)[1]), "+f"((d)[2]), "+f"((d)[3])        \
                 : "r"((a)[0]), "r"((a)[1]), "r"((a)[2]), "r"((a)[3]),           \
                   "r"(b0_), "r"(b1_))

// swizzled D-tile word index for logical (row r, col c)
__device__ __forceinline__ int dsw(int r, int c) {
    return r * DPW + ((((c >> 2) ^ (r & 31)) << 2) | (c & 3));
}
__device__ __forceinline__ bool ltp(float av, int ai, float bv, int bi) {
    return (av < bv) || (av == bv && ai < bi);
}
// ascending compare-exchange on packed keys (2 instr: min + max)
__device__ __forceinline__ void ceu(uint32_t& a, uint32_t& b) {
    uint32_t mn = min(a, b);
    b = max(a, b);
    a = mn;
}
__device__ __forceinline__ void sort4u(uint32_t (&k)[4]) {
    ceu(k[0], k[1]); ceu(k[2], k[3]);
    ceu(k[0], k[2]); ceu(k[1], k[3]);
    ceu(k[1], k[2]);
}
__device__ __forceinline__ float predict(float m1, float m2) {
    float d1 = sqrtf(fmaxf(m1, 0.f) + EPSQ);
    float d2 = sqrtf(fmaxf(m2, 0.f) + EPSQ);
    float e  = expf(d1);
    return (d1 / d2 < TLC) ? 2.f / (1.f + e) : 2.f / (1.f + LC * e);
}

// ---------------------------------------------------------------------------
// Kernel 1: fused bf16 convert + fp32 row norms (two rows per warp)
// ---------------------------------------------------------------------------
__global__ void convert_norms_kernel(const float* __restrict__ x) {
    if (blockIdx.x == 0 && threadIdx.x == 0) g_flagcnt = 0;
    int warp = (blockIdx.x * blockDim.x + threadIdx.x) >> 5;  // 0..8191
    int lane = threadIdx.x & 31;
    int r0 = warp * 2;
    const float* xr0 = x + (size_t)r0 * CDIM + lane * 8;
    const float* xr1 = xr0 + CDIM;
    float4 a0 = *(const float4*)xr0;
    float4 a1 = *(const float4*)(xr0 + 4);
    float4 b0 = *(const float4*)xr1;
    float4 b1 = *(const float4*)(xr1 + 4);

    float sa = a0.x*a0.x + a0.y*a0.y + a0.z*a0.z + a0.w*a0.w
             + a1.x*a1.x + a1.y*a1.y + a1.z*a1.z + a1.w*a1.w;
    float sb = b0.x*b0.x + b0.y*b0.y + b0.z*b0.z + b0.w*b0.w
             + b1.x*b1.x + b1.y*b1.y + b1.z*b1.z + b1.w*b1.w;

    __nv_bfloat162 p0(__float2bfloat16(a0.x), __float2bfloat16(a0.y));
    __nv_bfloat162 p1(__float2bfloat16(a0.z), __float2bfloat16(a0.w));
    __nv_bfloat162 p2(__float2bfloat16(a1.x), __float2bfloat16(a1.y));
    __nv_bfloat162 p3(__float2bfloat16(a1.z), __float2bfloat16(a1.w));
    uint4 u;
    u.x = *(uint32_t*)&p0; u.y = *(uint32_t*)&p1;
    u.z = *(uint32_t*)&p2; u.w = *(uint32_t*)&p3;
    ((uint4*)g_xhi)[(size_t)r0 * 32 + lane] = u;
    __nv_bfloat162 q0(__float2bfloat16(b0.x), __float2bfloat16(b0.y));
    __nv_bfloat162 q1(__float2bfloat16(b0.z), __float2bfloat16(b0.w));
    __nv_bfloat162 q2(__float2bfloat16(b1.x), __float2bfloat16(b1.y));
    __nv_bfloat162 q3(__float2bfloat16(b1.z), __float2bfloat16(b1.w));
    u.x = *(uint32_t*)&q0; u.y = *(uint32_t*)&q1;
    u.z = *(uint32_t*)&q2; u.w = *(uint32_t*)&q3;
    ((uint4*)g_xhi)[(size_t)(r0 + 1) * 32 + lane] = u;

    #pragma unroll
    for (int o = 16; o; o >>= 1) {
        sa += __shfl_xor_sync(0xffffffffu, sa, o);
        sb += __shfl_xor_sync(0xffffffffu, sb, o);
    }
    if (lane == 0) { g_norms[r0] = sa; g_norms[r0 + 1] = sb; }
}

// ---------------------------------------------------------------------------
// Kernel 2: single-pass bf16 Gram tile-pair + packed dual-index keys at
// D-write; extraction is pure load+sort+pop (2-task redux ILP, occ 2).
// ---------------------------------------------------------------------------
__global__ __launch_bounds__(512, 2)
void fcm_pair_kernel() {
    extern __shared__ __align__(16) char smem[];
    const uint32_t sbase = smem_u32(smem);

    const int tid  = threadIdx.x;
    const int lane = tid & 31;
    const int w    = tid >> 5;
    const int mw   = w >> 2;
    const int nw   = w & 3;
    const int b    = blockIdx.y;

    int p = blockIdx.x;
    int i = (int)((65.0f - sqrtf(4225.0f - 8.0f * (float)p)) * 0.5f);
    while ((i + 1) * (65 - (i + 1)) / 2 <= p) ++i;
    while (i * (65 - i) / 2 > p) --i;
    const int j = i + (p - i * (65 - i) / 2);
    const int row0 = i * 128, col0 = j * 128;
    const bool diag = (i == j);

    const __nv_bfloat16* xb = g_xhi + (size_t)b * HW * CDIM;
    const int lrow = ((lane >> 3) & 1) * 8 + (lane & 7);
    const int lkb  = (lane >> 4) * 16;

    auto stage = [&](int kc) {
        const uint32_t dst = sbase + (uint32_t)((kc & 1) * STAGEB);
        #pragma unroll
        for (int o = 0; o < 2; ++o) {
            int lin = tid + o * 512;
            int r = lin >> 3, gg = lin & 7;
            cp16(dst + (uint32_t)(r * SROWB + gg * 16),
                 xb + (size_t)(row0 + r) * CDIM + kc * 64 + gg * 8);
            cp16(dst + TENB + (uint32_t)(r * SROWB + gg * 16),
                 xb + (size_t)(col0 + r) * CDIM + kc * 64 + gg * 8);
        }
        cp_commit();
    };
    stage(0);

    float acc[2][4][4];
    #pragma unroll
    for (int mf = 0; mf < 2; ++mf)
        #pragma unroll
        for (int nf = 0; nf < 4; ++nf)
            #pragma unroll
            for (int e = 0; e < 4; ++e) acc[mf][nf][e] = 0.f;

    for (int kc = 0; kc < 4; ++kc) {
        cp_wait<0>();
        __syncthreads();
        if (kc < 3) stage(kc + 1);
        const uint32_t bb  = sbase + (uint32_t)((kc & 1) * STAGEB);
        const uint32_t ab  = bb + (uint32_t)((mw * 32 + lrow) * SROWB);
        const uint32_t bbs = bb + TENB + (uint32_t)((nw * 32 + lrow) * SROWB);
        #pragma unroll
        for (int ks = 0; ks < 4; ++ks) {
            const uint32_t kb = (uint32_t)(ks * 32 + lkb);
            uint32_t ah[2][4], bh[2][4];
            ldsm_x4(ah[0], ab + kb);
            ldsm_x4(ah[1], ab + 16 * SROWB + kb);
            ldsm_x4(bh[0], bbs + kb);
            ldsm_x4(bh[1], bbs + 16 * SROWB + kb);
            #pragma unroll
            for (int mf = 0; mf < 2; ++mf)
                #pragma unroll
                for (int nf = 0; nf < 4; ++nf)
                    MMA16816(acc[mf][nf], ah[mf],
                             bh[nf >> 1][nf & 1], bh[nf >> 1][(nf & 1) + 2]);
        }
    }
    __syncthreads();                 // ldsm done; alias smem as key D-tile

    // ---- packed dual-index keys into swizzled SMEM ----
    // key = (Dbits & VMASK) | (row_local << 7) | col_local ; diag elem = ~0
    uint32_t* Dt = (uint32_t*)smem;
    #pragma unroll
    for (int mf = 0; mf < 2; ++mf) {
        const int r0l = mw * 32 + mf * 16 + (lane >> 2);
        const float na0 = g_norms[b * HW + row0 + r0l];
        const float na1 = g_norms[b * HW + row0 + r0l + 8];
        const float* nbp = g_norms + b * HW + col0 + nw * 32 + (lane & 3) * 2;
        #pragma unroll
        for (int nf = 0; nf < 4; ++nf) {
            float2 nb = *(const float2*)(nbp + nf * 8);
            const int cl = nw * 32 + nf * 8 + (lane & 3) * 2;
            uint32_t k00 = (__float_as_uint(na0 + nb.x - 2.f * acc[mf][nf][0]) & VMASK)
                         | ((uint32_t)r0l << 7) | (uint32_t)cl;
            uint32_t k01 = (__float_as_uint(na0 + nb.y - 2.f * acc[mf][nf][1]) & VMASK)
                         | ((uint32_t)r0l << 7) | (uint32_t)(cl + 1);
            uint32_t k10 = (__float_as_uint(na1 + nb.x - 2.f * acc[mf][nf][2]) & VMASK)
                         | ((uint32_t)(r0l + 8) << 7) | (uint32_t)cl;
            uint32_t k11 = (__float_as_uint(na1 + nb.y - 2.f * acc[mf][nf][3]) & VMASK)
                         | ((uint32_t)(r0l + 8) << 7) | (uint32_t)(cl + 1);
            if (diag) {
                if (r0l == cl)         k00 = 0xFFFFFFFFu;
                if (r0l == cl + 1)     k01 = 0xFFFFFFFFu;
                if (r0l + 8 == cl)     k10 = 0xFFFFFFFFu;
                if (r0l + 8 == cl + 1) k11 = 0xFFFFFFFFu;
            }
            *(uint2*)&Dt[dsw(r0l, cl)]     = make_uint2(k00, k01);
            *(uint2*)&Dt[dsw(r0l + 8, cl)] = make_uint2(k10, k11);
        }
    }
    __syncthreads();

    // ---- top-4 extraction: 2 tasks/iter, pure load+sort+pop ----
    const int ntask = diag ? 128 : 256;
    for (int t0 = w; t0 < ntask; t0 += 32) {
        uint32_t k[2][4];
        bool isrow[2];
        #pragma unroll
        for (int u = 0; u < 2; ++u) {
            const int t = t0 + 16 * u;
            isrow[u] = (t < 128);
            if (isrow[u]) {                             // row task: keys direct
                const int rr = t;
                const uint4 dv =
                    *(const uint4*)&Dt[rr * DPW + ((lane ^ (rr & 31)) << 2)];
                k[u][0] = dv.x; k[u][1] = dv.y; k[u][2] = dv.z; k[u][3] = dv.w;
            } else {                                    // col task: keys direct
                const int cc = t - 128;
                const int cb = cc >> 2, cq = cc & 3;
                #pragma unroll
                for (int q = 0; q < 4; ++q) {
                    const int r = lane + 32 * q;
                    k[u][q] = Dt[r * DPW + (((cb ^ (r & 31)) << 2) | cq)];
                }
            }
            sort4u(k[u]);
        }

        uint32_t myk[2];
        #pragma unroll
        for (int pp = 0; pp < 4; ++pp) {
            uint32_t g0 = redux_min_u32(k[0][0]);
            uint32_t g1 = redux_min_u32(k[1][0]);
            if (lane == pp) { myk[0] = g0; myk[1] = g1; }
            if (k[0][0] == g0) {
                k[0][0] = k[0][1]; k[0][1] = k[0][2];
                k[0][2] = k[0][3]; k[0][3] = 0xFFFFFFFFu;
            }
            if (k[1][0] == g1) {
                k[1][0] = k[1][1]; k[1][1] = k[1][2];
                k[1][2] = k[1][3]; k[1][3] = 0xFFFFFFFFu;
            }
        }
        if (lane < 4) {
            #pragma unroll
            for (int u = 0; u < 2; ++u) {
                const int t = t0 + 16 * u;
                const int grow = isrow[u] ? (row0 + t) : (col0 + (t - 128));
                const int slot = isrow[u] ? j : i;
                // col tasks: local index = row bits -> move to low 7 bits
                uint32_t kk = isrow[u] ? myk[u]
                    : ((myk[u] & VMASK) | ((myk[u] >> 7) & 0x7Fu));
                g_pc[(((size_t)(b * HW + grow)) * NSTRIP + slot) * 4 + lane] = kk;
            }
        }
    }
}

// ---------------------------------------------------------------------------
// Kernel 3: warp-per-row merge (packed-key pop-min over 32 slot lists) +
// exact fp32 refinement of 8 candidates (batched shfl reduction) + flagging.
// ---------------------------------------------------------------------------
__global__ void merge_refine_kernel(const float* __restrict__ x,
                                    float* __restrict__ out, int out_size) {
    int gw   = (blockIdx.x * blockDim.x + threadIdx.x) >> 5;
    int lane = threadIdx.x & 31;
    if (gw >= BATCH * HW) return;
    const int b = gw >> 12, rl = gw & 4095;

    const uint4 kk = *(const uint4*)(g_pc + ((size_t)gw * NSTRIP + lane) * 4);

    // B1 = min over tiles of the stored 4th-smallest value (lower bound)
    const uint32_t b1 = redux_min_u32(kk.w & VMASK);

    // repack: 18-bit value | 12-bit global index (slot*128 + idx7); re-sort
    const uint32_t base = (uint32_t)lane * 128u;
    uint32_t mk[4];
    mk[0] = (kk.x & VMASK) | (base + (kk.x & 0x7Fu));
    mk[1] = (kk.y & VMASK) | (base + (kk.y & 0x7Fu));
    mk[2] = (kk.z & VMASK) | (base + (kk.z & 0x7Fu));
    mk[3] = (kk.w & VMASK) | (base + (kk.w & 0x7Fu));
    sort4u(mk);

    uint32_t gks[8];
    #pragma unroll
    for (int pp = 0; pp < 8; ++pp) {
        uint32_t gv = redux_min_u32(mk[0]);
        gks[pp] = gv;
        if (mk[0] == gv) {
            mk[0] = mk[1]; mk[1] = mk[2]; mk[2] = mk[3]; mk[3] = 0xFFFFFFFFu;
        }
    }

    // exact fp32 refinement: batched partial sums, one interleaved reduction
    const float* xb = x + (size_t)b * HW * CDIM;
    const float* xr = xb + (size_t)rl * CDIM + lane * 8;
    float4 a0 = *(const float4*)xr;
    float4 a1 = *(const float4*)(xr + 4);
    const float nr = g_norms[b * HW + rl];

    float s[8];
    #pragma unroll
    for (int k = 0; k < 8; ++k) {
        const int c = (int)(gks[k] & 0xFFFu);
        const float* xc = xb + (size_t)c * CDIM + lane * 8;
        float4 c0 = *(const float4*)xc;
        float4 c1 = *(const float4*)(xc + 4);
        s[k] = a0.x*c0.x + a0.y*c0.y + a0.z*c0.z + a0.w*c0.w
             + a1.x*c1.x + a1.y*c1.y + a1.z*c1.z + a1.w*c1.w;
    }
    #pragma unroll
    for (int off = 16; off; off >>= 1) {
        #pragma unroll
        for (int k = 0; k < 8; ++k)
            s[k] += __shfl_xor_sync(0xffffffffu, s[k], off);
    }

    float m1 = FLT_MAX, m2 = FLT_MAX; int j1 = 0, j2 = 0;
    #pragma unroll
    for (int k = 0; k < 8; ++k) {
        const int c = (int)(gks[k] & 0xFFFu);
        float D = nr + g_norms[b * HW + c] - 2.f * s[k];
        if (ltp(D, c, m1, j1)) { m2 = m1; j2 = j1; m1 = D; j1 = c; }
        else if (ltp(D, c, m2, j2)) { m2 = D; j2 = c; }
    }

    if (lane == 0) {
        out[(size_t)b * HW + rl] = predict(m1, m2);
        if (out_size >= 2 * BATCH * HW)
            out[(size_t)BATCH * HW + (size_t)b * HW + rl] = (float)j1;
        // stored values are lower bounds of bf16 D; exact >= bound - MARGIN
        float bound = fminf(__uint_as_float(b1),
                            __uint_as_float(gks[7] & VMASK));
        if (m2 > bound - MARGIN) {
            int fi = atomicAdd(&g_flagcnt, 1);
            g_flaglist[fi] = gw;
        }
    }
}

// ---------------------------------------------------------------------------
// Kernel 4: exact full-row rescan for flagged rows (expected ~0 rows).
// ---------------------------------------------------------------------------
__global__ void fallback_kernel(const float* __restrict__ x,
                                float* __restrict__ out, int out_size) {
    __shared__ float sv1[256], sv2[256];
    __shared__ int   si1[256];
    const int n = g_flagcnt;
    for (int fi = blockIdx.x; fi < n; fi += gridDim.x) {
        const int rowg = g_flaglist[fi];
        const int b = rowg >> 12, r = rowg & 4095;
        const float* xb = x + (size_t)b * HW * CDIM;
        const float* xr = xb + (size_t)r * CDIM;
        const float  nr = g_norms[rowg];
        float v1 = FLT_MAX, v2 = FLT_MAX; int i1 = 0x7fffffff;
        for (int c = threadIdx.x; c < HW; c += 256) {
            if (c == r) continue;
            const float4* xc = (const float4*)(xb + (size_t)c * CDIM);
            float s = 0.f;
            #pragma unroll
            for (int d = 0; d < 64; ++d) {
                float4 va = ((const float4*)xr)[d];
                float4 vb = xc[d];
                s += va.x*vb.x + va.y*vb.y + va.z*vb.z + va.w*vb.w;
            }
            float D = nr + g_norms[b * HW + c] - 2.f * s;
            if (ltp(D, c, v1, i1)) { v2 = v1; v1 = D; i1 = c; }
            else if (D < v2) { v2 = D; }
        }
        sv1[threadIdx.x] = v1; sv2[threadIdx.x] = v2; si1[threadIdx.x] = i1;
        __syncthreads();
        for (int off = 128; off; off >>= 1) {
            if (threadIdx.x < off) {
                float b1 = sv1[threadIdx.x + off], b2 = sv2[threadIdx.x + off];
                int   bi = si1[threadIdx.x + off];
                float a1v = sv1[threadIdx.x]; int a1i = si1[threadIdx.x];
                if (ltp(b1, bi, a1v, a1i)) {
                    sv2[threadIdx.x] = fminf(a1v, b2);
                    sv1[threadIdx.x] = b1; si1[threadIdx.x] = bi;
                } else {
                    sv2[threadIdx.x] = fminf(sv2[threadIdx.x], b1);
                }
            }
            __syncthreads();
        }
        if (threadIdx.x == 0) {
            out[(size_t)b * HW + r] = predict(sv1[0], sv2[0]);
            if (out_size >= 2 * BATCH * HW)
                out[(size_t)BATCH * HW + (size_t)b * HW + r] = (float)si1[0];
        }
        __syncthreads();
    }
}

// ---------------------------------------------------------------------------
extern "C" void kernel_launch(void* const* d_in, const int* in_sizes, int n_in,
                              void* d_out, int out_size) {
    const float* x   = (const float*)d_in[0];
    float*       out = (float*)d_out;

    convert_norms_kernel<<<BATCH * HW / 16, 256>>>(x);

    cudaFuncSetAttribute(fcm_pair_kernel,
                         cudaFuncAttributeMaxDynamicSharedMemorySize, TOTSMEM);
    dim3 grid(NPAIR, BATCH);
    fcm_pair_kernel<<<grid, 512, TOTSMEM>>>();

    merge_refine_kernel<<<BATCH * HW / 8, 256>>>(x, out, out_size);
    fallback_kernel<<<64, 256>>>(x, out, out_size);
}

// round 15
// speedup vs baseline: 1.3344x; 1.0180x over previous
#include <cuda_runtime.h>
#include <cuda_bf16.h>
#include <cstdint>
#include <float.h>
#include <math.h>

#define BATCH 4
#define HW    4096
#define CDIM  256
#define NSTRIP 32
#define NPAIR  528
#define EPSQ  1e-9f
#define TLC   0.6f
#define LC    2.0f
#define MARGIN 0.75f
#define VMASK 0xFFFFC000u         // 18-bit value field (low 14 bits = row|col)
#define CHB   16384               // one 128x64 bf16 chunk (128B rows, XOR swizzled)
#define BUFB  (2 * CHB)           // A chunk + B chunk per buffer
#define TOTSMEM (2 * BUFB)        // 65536 B double-buffered (Dt aliases all)
#define DPW   128                 // D-tile words per row (XOR-swizzled blocks)

// static device scratch. g_xhi layout: [b][strip][kc][chunk 16KB], swizzle baked.
__device__ __align__(128) __nv_bfloat16 g_xhi[BATCH * HW * CDIM];
__device__ float    g_norms[BATCH * HW];
__device__ uint32_t g_pc[(size_t)BATCH * HW * NSTRIP * 4];  // packed (val18|..|idx7)
__device__ int      g_flagcnt;
__device__ int      g_flaglist[BATCH * HW];

// ---------------------------------------------------------------------------
__device__ __forceinline__ uint32_t smem_u32(const void* p) {
    uint32_t a;
    asm("{ .reg .u64 t; cvta.to.shared.u64 t, %1; cvt.u32.u64 %0, t; }"
        : "=r"(a) : "l"(p));
    return a;
}
__device__ __forceinline__ void ldsm_x4(uint32_t (&r)[4], uint32_t addr) {
    asm volatile("ldmatrix.sync.aligned.m8n8.x4.shared.b16 {%0,%1,%2,%3}, [%4];"
                 : "=r"(r[0]), "=r"(r[1]), "=r"(r[2]), "=r"(r[3]) : "r"(addr));
}
__device__ __forceinline__ uint32_t redux_min_u32(uint32_t v) {
    uint32_t r;
    asm volatile("redux.sync.min.u32 %0, %1, 0xffffffff;" : "=r"(r) : "r"(v));
    return r;
}
#define MMA16816(d, a, b0_, b1_)                                                 \
    asm volatile("mma.sync.aligned.m16n8k16.row.col.f32.bf16.bf16.f32 "          \
                 "{%0,%1,%2,%3}, {%4,%5,%6,%7}, {%8,%9}, {%0,%1,%2,%3};"         \
                 : "+f"((d)[0]), "+f"((d)[1]), "+f"((d)[2]), "+f"((d)[3])        \
                 : "r"((a)[0]), "r"((a)[1]), "r"((a)[2]), "r"((a)[3]),           \
                   "r"(b0_), "r"(b1_))

#define MBARRIER_INIT(mbar, cnt) \
    asm volatile("mbarrier.init.shared.b64 [%0], %1;" \
                 :: "r"((uint32_t)(mbar)), "r"((uint32_t)(cnt)) : "memory")
#define MBARRIER_EXPECT_TX(mbar, tx) \
    asm volatile("mbarrier.arrive.expect_tx.shared.b64 _, [%0], %1;" \
                 :: "r"((uint32_t)(mbar)), "r"((uint32_t)(tx)) : "memory")
#define MBARRIER_WAIT_PARITY(mbar, parity) do {                                     \
    uint32_t _m = (uint32_t)(mbar); uint32_t _p = (uint32_t)(parity);               \
    asm volatile("{\n .reg .pred P1;\n"                                             \
                 "WAIT_LOOP_%=:\n"                                                  \
                 " mbarrier.try_wait.parity.acquire.cta.shared::cta.b64 P1,[%0],%1,0x989680;\n" \
                 " @P1 bra.uni WAIT_DONE_%=;\n"                                     \
                 " bra.uni WAIT_LOOP_%=;\n"                                         \
                 "WAIT_DONE_%=:\n}"                                                 \
                 :: "r"(_m), "r"(_p) : "memory");                                   \
} while (0)
#define BULK_G2S(dst, src, bytes, mbar) \
    asm volatile("cp.async.bulk.shared::cta.global.mbarrier::complete_tx::bytes " \
                 "[%0], [%1], %2, [%3];" \
                 :: "r"((uint32_t)(dst)), "l"(src), "r"((uint32_t)(bytes)), \
                    "r"((uint32_t)(mbar)) : "memory")

// swizzled D-tile word index for logical (row r, col c)
__device__ __forceinline__ int dsw(int r, int c) {
    return r * DPW + ((((c >> 2) ^ (r & 31)) << 2) | (c & 3));
}
__device__ __forceinline__ bool ltp(float av, int ai, float bv, int bi) {
    return (av < bv) || (av == bv && ai < bi);
}
__device__ __forceinline__ void ceu(uint32_t& a, uint32_t& b) {
    uint32_t mn = min(a, b);
    b = max(a, b);
    a = mn;
}
__device__ __forceinline__ void sort4u(uint32_t (&k)[4]) {
    ceu(k[0], k[1]); ceu(k[2], k[3]);
    ceu(k[0], k[2]); ceu(k[1], k[3]);
    ceu(k[1], k[2]);
}
__device__ __forceinline__ float predict(float m1, float m2) {
    float d1 = sqrtf(fmaxf(m1, 0.f) + EPSQ);
    float d2 = sqrtf(fmaxf(m2, 0.f) + EPSQ);
    float e  = expf(d1);
    return (d1 / d2 < TLC) ? 2.f / (1.f + e) : 2.f / (1.f + LC * e);
}

// ---------------------------------------------------------------------------
// Kernel 1: fused bf16 convert (to swizzled chunk layout) + fp32 row norms.
// Two rows per warp; lane covers 16B group: chunk kc = lane>>3, group = lane&7.
// ---------------------------------------------------------------------------
__global__ void convert_norms_kernel(const float* __restrict__ x) {
    if (blockIdx.x == 0 && threadIdx.x == 0) g_flagcnt = 0;
    int warp = (blockIdx.x * blockDim.x + threadIdx.x) >> 5;  // 0..8191
    int lane = threadIdx.x & 31;
    int gw0 = warp * 2;                                       // global rows
    const float* xr0 = x + (size_t)gw0 * CDIM + lane * 8;
    const float* xr1 = xr0 + CDIM;
    float4 a0 = *(const float4*)xr0;
    float4 a1 = *(const float4*)(xr0 + 4);
    float4 b0 = *(const float4*)xr1;
    float4 b1 = *(const float4*)(xr1 + 4);

    float sa = a0.x*a0.x + a0.y*a0.y + a0.z*a0.z + a0.w*a0.w
             + a1.x*a1.x + a1.y*a1.y + a1.z*a1.z + a1.w*a1.w;
    float sb = b0.x*b0.x + b0.y*b0.y + b0.z*b0.z + b0.w*b0.w
             + b1.x*b1.x + b1.y*b1.y + b1.z*b1.z + b1.w*b1.w;

    const int kc = lane >> 3, gg = lane & 7;
    char* xh = (char*)g_xhi;
    // row gw: b = gw>>12, strip = (gw>>7)&31, r = gw&127
    auto chunk_off = [&](int gw) -> size_t {
        int r = gw & 127;
        return (size_t)(((gw >> 7) * 4) + kc) * CHB
             + (size_t)(r * 128 + (((gg ^ (r & 7))) << 4));
    };

    __nv_bfloat162 p0(__float2bfloat16(a0.x), __float2bfloat16(a0.y));
    __nv_bfloat162 p1(__float2bfloat16(a0.z), __float2bfloat16(a0.w));
    __nv_bfloat162 p2(__float2bfloat16(a1.x), __float2bfloat16(a1.y));
    __nv_bfloat162 p3(__float2bfloat16(a1.z), __float2bfloat16(a1.w));
    uint4 u;
    u.x = *(uint32_t*)&p0; u.y = *(uint32_t*)&p1;
    u.z = *(uint32_t*)&p2; u.w = *(uint32_t*)&p3;
    *(uint4*)(xh + chunk_off(gw0)) = u;
    __nv_bfloat162 q0(__float2bfloat16(b0.x), __float2bfloat16(b0.y));
    __nv_bfloat162 q1(__float2bfloat16(b0.z), __float2bfloat16(b0.w));
    __nv_bfloat162 q2(__float2bfloat16(b1.x), __float2bfloat16(b1.y));
    __nv_bfloat162 q3(__float2bfloat16(b1.z), __float2bfloat16(b1.w));
    u.x = *(uint32_t*)&q0; u.y = *(uint32_t*)&q1;
    u.z = *(uint32_t*)&q2; u.w = *(uint32_t*)&q3;
    *(uint4*)(xh + chunk_off(gw0 + 1)) = u;

    #pragma unroll
    for (int o = 16; o; o >>= 1) {
        sa += __shfl_xor_sync(0xffffffffu, sa, o);
        sb += __shfl_xor_sync(0xffffffffu, sb, o);
    }
    if (lane == 0) { g_norms[gw0] = sa; g_norms[gw0 + 1] = sb; }
}

// ---------------------------------------------------------------------------
// Kernel 2: single-pass bf16 Gram tile-pair, bulk-async staging (2 copies/kc),
// packed dual-index keys, 2-task redux extraction. Occupancy 2.
// ---------------------------------------------------------------------------
__global__ __launch_bounds__(512, 2)
void fcm_pair_kernel() {
    extern __shared__ __align__(128) char smem[];
    __shared__ __align__(8) unsigned long long s_mbar[2];
    const uint32_t sbase = smem_u32(smem);
    const uint32_t mb0 = smem_u32(&s_mbar[0]);
    const uint32_t mb1 = smem_u32(&s_mbar[1]);

    const int tid  = threadIdx.x;
    const int lane = tid & 31;
    const int w    = tid >> 5;
    const int mw   = w >> 2;
    const int nw   = w & 3;
    const int b    = blockIdx.y;

    int p = blockIdx.x;
    int i = (int)((65.0f - sqrtf(4225.0f - 8.0f * (float)p)) * 0.5f);
    while ((i + 1) * (65 - (i + 1)) / 2 <= p) ++i;
    while (i * (65 - i) / 2 > p) --i;
    const int j = i + (p - i * (65 - i) / 2);
    const int row0 = i * 128, col0 = j * 128;
    const bool diag = (i == j);

    const char* xch = (const char*)g_xhi + (size_t)b * (NSTRIP * 4) * CHB;
    const int lrow = ((lane >> 3) & 1) * 8 + (lane & 7);
    const int hi16 = lane >> 4;

    if (tid == 0) { MBARRIER_INIT(mb0, 1); MBARRIER_INIT(mb1, 1); }
    __syncthreads();

    auto stage = [&](int kc) {    // tid==0 only
        const int buf = kc & 1;
        const uint32_t mb = buf ? mb1 : mb0;
        const uint32_t dst = sbase + (uint32_t)(buf * BUFB);
        MBARRIER_EXPECT_TX(mb, diag ? CHB : 2 * CHB);
        BULK_G2S(dst, xch + (size_t)(i * 4 + kc) * CHB, CHB, mb);
        if (!diag)
            BULK_G2S(dst + CHB, xch + (size_t)(j * 4 + kc) * CHB, CHB, mb);
    };
    if (tid == 0) stage(0);

    float acc[2][4][4];
    #pragma unroll
    for (int mf = 0; mf < 2; ++mf)
        #pragma unroll
        for (int nf = 0; nf < 4; ++nf)
            #pragma unroll
            for (int e = 0; e < 4; ++e) acc[mf][nf][e] = 0.f;

    int ph0 = 0, ph1 = 0;
    for (int kc = 0; kc < 4; ++kc) {
        if (kc & 1) { MBARRIER_WAIT_PARITY(mb1, ph1); ph1 ^= 1; }
        else        { MBARRIER_WAIT_PARITY(mb0, ph0); ph0 ^= 1; }
        __syncthreads();                  // all warps past prior chunk's ldsm
        if (kc < 3 && tid == 0) stage(kc + 1);

        const uint32_t abase = sbase + (uint32_t)((kc & 1) * BUFB);
        const uint32_t bbase = diag ? abase : abase + CHB;
        const int ra = mw * 32 + lrow;
        const int rb = nw * 32 + lrow;
        const uint32_t am = (uint32_t)(lrow & 7);
        #pragma unroll
        for (int ks = 0; ks < 4; ++ks) {
            const uint32_t goff = (((uint32_t)(ks * 2 + hi16) ^ am) << 4);
            uint32_t ah[2][4], bh[2][4];
            ldsm_x4(ah[0], abase + (uint32_t)(ra * 128) + goff);
            ldsm_x4(ah[1], abase + (uint32_t)((ra + 16) * 128) + goff);
            ldsm_x4(bh[0], bbase + (uint32_t)(rb * 128) + goff);
            ldsm_x4(bh[1], bbase + (uint32_t)((rb + 16) * 128) + goff);
            #pragma unroll
            for (int mf = 0; mf < 2; ++mf)
                #pragma unroll
                for (int nf = 0; nf < 4; ++nf)
                    MMA16816(acc[mf][nf], ah[mf],
                             bh[nf >> 1][nf & 1], bh[nf >> 1][(nf & 1) + 2]);
        }
    }
    __syncthreads();                 // ldsm done; alias smem as key D-tile

    // ---- packed dual-index keys into swizzled SMEM ----
    uint32_t* Dt = (uint32_t*)smem;
    #pragma unroll
    for (int mf = 0; mf < 2; ++mf) {
        const int r0l = mw * 32 + mf * 16 + (lane >> 2);
        const float na0 = g_norms[b * HW + row0 + r0l];
        const float na1 = g_norms[b * HW + row0 + r0l + 8];
        const float* nbp = g_norms + b * HW + col0 + nw * 32 + (lane & 3) * 2;
        #pragma unroll
        for (int nf = 0; nf < 4; ++nf) {
            float2 nb = *(const float2*)(nbp + nf * 8);
            const int cl = nw * 32 + nf * 8 + (lane & 3) * 2;
            uint32_t k00 = (__float_as_uint(na0 + nb.x - 2.f * acc[mf][nf][0]) & VMASK)
                         | ((uint32_t)r0l << 7) | (uint32_t)cl;
            uint32_t k01 = (__float_as_uint(na0 + nb.y - 2.f * acc[mf][nf][1]) & VMASK)
                         | ((uint32_t)r0l << 7) | (uint32_t)(cl + 1);
            uint32_t k10 = (__float_as_uint(na1 + nb.x - 2.f * acc[mf][nf][2]) & VMASK)
                         | ((uint32_t)(r0l + 8) << 7) | (uint32_t)cl;
            uint32_t k11 = (__float_as_uint(na1 + nb.y - 2.f * acc[mf][nf][3]) & VMASK)
                         | ((uint32_t)(r0l + 8) << 7) | (uint32_t)(cl + 1);
            if (diag) {
                if (r0l == cl)         k00 = 0xFFFFFFFFu;
                if (r0l == cl + 1)     k01 = 0xFFFFFFFFu;
                if (r0l + 8 == cl)     k10 = 0xFFFFFFFFu;
                if (r0l + 8 == cl + 1) k11 = 0xFFFFFFFFu;
            }
            *(uint2*)&Dt[dsw(r0l, cl)]     = make_uint2(k00, k01);
            *(uint2*)&Dt[dsw(r0l + 8, cl)] = make_uint2(k10, k11);
        }
    }
    __syncthreads();

    // ---- top-4 extraction: 2 tasks/iter, pure load+sort+pop ----
    const int ntask = diag ? 128 : 256;
    for (int t0 = w; t0 < ntask; t0 += 32) {
        uint32_t k[2][4];
        bool isrow[2];
        #pragma unroll
        for (int u = 0; u < 2; ++u) {
            const int t = t0 + 16 * u;
            isrow[u] = (t < 128);
            if (isrow[u]) {
                const int rr = t;
                const uint4 dv =
                    *(const uint4*)&Dt[rr * DPW + ((lane ^ (rr & 31)) << 2)];
                k[u][0] = dv.x; k[u][1] = dv.y; k[u][2] = dv.z; k[u][3] = dv.w;
            } else {
                const int cc = t - 128;
                const int cb = cc >> 2, cq = cc & 3;
                #pragma unroll
                for (int q = 0; q < 4; ++q) {
                    const int r = lane + 32 * q;
                    k[u][q] = Dt[r * DPW + (((cb ^ (r & 31)) << 2) | cq)];
                }
            }
            sort4u(k[u]);
        }

        uint32_t myk[2];
        #pragma unroll
        for (int pp = 0; pp < 4; ++pp) {
            uint32_t g0 = redux_min_u32(k[0][0]);
            uint32_t g1 = redux_min_u32(k[1][0]);
            if (lane == pp) { myk[0] = g0; myk[1] = g1; }
            if (k[0][0] == g0) {
                k[0][0] = k[0][1]; k[0][1] = k[0][2];
                k[0][2] = k[0][3]; k[0][3] = 0xFFFFFFFFu;
            }
            if (k[1][0] == g1) {
                k[1][0] = k[1][1]; k[1][1] = k[1][2];
                k[1][2] = k[1][3]; k[1][3] = 0xFFFFFFFFu;
            }
        }
        if (lane < 4) {
            #pragma unroll
            for (int u = 0; u < 2; ++u) {
                const int t = t0 + 16 * u;
                const int grow = isrow[u] ? (row0 + t) : (col0 + (t - 128));
                const int slot = isrow[u] ? j : i;
                uint32_t kk = isrow[u] ? myk[u]
                    : ((myk[u] & VMASK) | ((myk[u] >> 7) & 0x7Fu));
                g_pc[(((size_t)(b * HW + grow)) * NSTRIP + slot) * 4 + lane] = kk;
            }
        }
    }
}

// ---------------------------------------------------------------------------
// Kernel 3: warp-per-row merge + exact fp32 refinement of 8 candidates.
// ---------------------------------------------------------------------------
__global__ void merge_refine_kernel(const float* __restrict__ x,
                                    float* __restrict__ out, int out_size) {
    int gw   = (blockIdx.x * blockDim.x + threadIdx.x) >> 5;
    int lane = threadIdx.x & 31;
    if (gw >= BATCH * HW) return;
    const int b = gw >> 12, rl = gw & 4095;

    const uint4 kk = *(const uint4*)(g_pc + ((size_t)gw * NSTRIP + lane) * 4);
    const uint32_t b1 = redux_min_u32(kk.w & VMASK);

    const uint32_t base = (uint32_t)lane * 128u;
    uint32_t mk[4];
    mk[0] = (kk.x & VMASK) | (base + (kk.x & 0x7Fu));
    mk[1] = (kk.y & VMASK) | (base + (kk.y & 0x7Fu));
    mk[2] = (kk.z & VMASK) | (base + (kk.z & 0x7Fu));
    mk[3] = (kk.w & VMASK) | (base + (kk.w & 0x7Fu));
    sort4u(mk);

    uint32_t gks[8];
    #pragma unroll
    for (int pp = 0; pp < 8; ++pp) {
        uint32_t gv = redux_min_u32(mk[0]);
        gks[pp] = gv;
        if (mk[0] == gv) {
            mk[0] = mk[1]; mk[1] = mk[2]; mk[2] = mk[3]; mk[3] = 0xFFFFFFFFu;
        }
    }

    const float* xb = x + (size_t)b * HW * CDIM;
    const float* xr = xb + (size_t)rl * CDIM + lane * 8;
    float4 a0 = *(const float4*)xr;
    float4 a1 = *(const float4*)(xr + 4);
    const float nr = g_norms[b * HW + rl];

    float s[8];
    #pragma unroll
    for (int k = 0; k < 8; ++k) {
        const int c = (int)(gks[k] & 0xFFFu);
        const float* xc = xb + (size_t)c * CDIM + lane * 8;
        float4 c0 = *(const float4*)xc;
        float4 c1 = *(const float4*)(xc + 4);
        s[k] = a0.x*c0.x + a0.y*c0.y + a0.z*c0.z + a0.w*c0.w
             + a1.x*c1.x + a1.y*c1.y + a1.z*c1.z + a1.w*c1.w;
    }
    #pragma unroll
    for (int off = 16; off; off >>= 1) {
        #pragma unroll
        for (int k = 0; k < 8; ++k)
            s[k] += __shfl_xor_sync(0xffffffffu, s[k], off);
    }

    float m1 = FLT_MAX, m2 = FLT_MAX; int j1 = 0, j2 = 0;
    #pragma unroll
    for (int k = 0; k < 8; ++k) {
        const int c = (int)(gks[k] & 0xFFFu);
        float D = nr + g_norms[b * HW + c] - 2.f * s[k];
        if (ltp(D, c, m1, j1)) { m2 = m1; j2 = j1; m1 = D; j1 = c; }
        else if (ltp(D, c, m2, j2)) { m2 = D; j2 = c; }
    }

    if (lane == 0) {
        out[(size_t)b * HW + rl] = predict(m1, m2);
        if (out_size >= 2 * BATCH * HW)
            out[(size_t)BATCH * HW + (size_t)b * HW + rl] = (float)j1;
        float bound = fminf(__uint_as_float(b1),
                            __uint_as_float(gks[7] & VMASK));
        if (m2 > bound - MARGIN) {
            int fi = atomicAdd(&g_flagcnt, 1);
            g_flaglist[fi] = gw;
        }
    }
}

// ---------------------------------------------------------------------------
// Kernel 4: exact full-row rescan for flagged rows (expected ~0 rows).
// ---------------------------------------------------------------------------
__global__ void fallback_kernel(const float* __restrict__ x,
                                float* __restrict__ out, int out_size) {
    __shared__ float sv1[256], sv2[256];
    __shared__ int   si1[256];
    const int n = g_flagcnt;
    for (int fi = blockIdx.x; fi < n; fi += gridDim.x) {
        const int rowg = g_flaglist[fi];
        const int b = rowg >> 12, r = rowg & 4095;
        const float* xb = x + (size_t)b * HW * CDIM;
        const float* xr = xb + (size_t)r * CDIM;
        const float  nr = g_norms[rowg];
        float v1 = FLT_MAX, v2 = FLT_MAX; int i1 = 0x7fffffff;
        for (int c = threadIdx.x; c < HW; c += 256) {
            if (c == r) continue;
            const float4* xc = (const float4*)(xb + (size_t)c * CDIM);
            float s = 0.f;
            #pragma unroll
            for (int d = 0; d < 64; ++d) {
                float4 va = ((const float4*)xr)[d];
                float4 vb = xc[d];
                s += va.x*vb.x + va.y*vb.y + va.z*vb.z + va.w*vb.w;
            }
            float D = nr + g_norms[b * HW + c] - 2.f * s;
            if (ltp(D, c, v1, i1)) { v2 = v1; v1 = D; i1 = c; }
            else if (D < v2) { v2 = D; }
        }
        sv1[threadIdx.x] = v1; sv2[threadIdx.x] = v2; si1[threadIdx.x] = i1;
        __syncthreads();
        for (int off = 128; off; off >>= 1) {
            if (threadIdx.x < off) {
                float b1 = sv1[threadIdx.x + off], b2 = sv2[threadIdx.x + off];
                int   bi = si1[threadIdx.x + off];
                float a1v = sv1[threadIdx.x]; int a1i = si1[threadIdx.x];
                if (ltp(b1, bi, a1v, a1i)) {
                    sv2[threadIdx.x] = fminf(a1v, b2);
                    sv1[threadIdx.x] = b1; si1[threadIdx.x] = bi;
                } else {
                    sv2[threadIdx.x] = fminf(sv2[threadIdx.x], b1);
                }
            }
            __syncthreads();
        }
        if (threadIdx.x == 0) {
            out[(size_t)b * HW + r] = predict(sv1[0], sv2[0]);
            if (out_size >= 2 * BATCH * HW)
                out[(size_t)BATCH * HW + (size_t)b * HW + r] = (float)si1[0];
        }
        __syncthreads();
    }
}

// ---------------------------------------------------------------------------
extern "C" void kernel_launch(void* const* d_in, const int* in_sizes, int n_in,
                              void* d_out, int out_size) {
    const float* x   = (const float*)d_in[0];
    float*       out = (float*)d_out;

    convert_norms_kernel<<<BATCH * HW / 16, 256>>>(x);

    cudaFuncSetAttribute(fcm_pair_kernel,
                         cudaFuncAttributeMaxDynamicSharedMemorySize, TOTSMEM);
    dim3 grid(NPAIR, BATCH);
    fcm_pair_kernel<<<grid, 512, TOTSMEM>>>();

    merge_refine_kernel<<<BATCH * HW / 8, 256>>>(x, out, out_size);
    fallback_kernel<<<64, 256>>>(x, out, out_size);
}

// round 16
// speedup vs baseline: 1.3582x; 1.0178x over previous
#include <cuda_runtime.h>
#include <cuda_bf16.h>
#include <cstdint>
#include <float.h>
#include <math.h>

#define BATCH 4
#define HW    4096
#define CDIM  256
#define NSTRIP 32
#define NPAIR  528
#define EPSQ  1e-9f
#define TLC   0.6f
#define LC    2.0f
#define MARGIN 0.75f
#define VMASK 0xFFFFC000u         // 18-bit value field (low 14 bits = row|col)
#define CHB   16384               // one 128x64 bf16 chunk (128B rows, XOR swizzled)
#define BUFB  (2 * CHB)           // A chunk + B chunk per buffer
#define TOTSMEM (2 * BUFB)        // 65536 B double-buffered (Dt aliases all)
#define DPW   128                 // D-tile words per row (XOR-swizzled blocks)

// static device scratch. g_xhi layout: [b][strip][kc][chunk 16KB], swizzle baked.
__device__ __align__(128) __nv_bfloat16 g_xhi[BATCH * HW * CDIM];
__device__ float    g_norms[BATCH * HW];
__device__ uint32_t g_pc[(size_t)BATCH * HW * NSTRIP * 4];  // packed (val18|..|idx7)
__device__ int      g_flagcnt;
__device__ int      g_flaglist[BATCH * HW];

// ---------------------------------------------------------------------------
__device__ __forceinline__ uint32_t smem_u32(const void* p) {
    uint32_t a;
    asm("{ .reg .u64 t; cvta.to.shared.u64 t, %1; cvt.u32.u64 %0, t; }"
        : "=r"(a) : "l"(p));
    return a;
}
__device__ __forceinline__ void ldsm_x4(uint32_t (&r)[4], uint32_t addr) {
    asm volatile("ldmatrix.sync.aligned.m8n8.x4.shared.b16 {%0,%1,%2,%3}, [%4];"
                 : "=r"(r[0]), "=r"(r[1]), "=r"(r[2]), "=r"(r[3]) : "r"(addr));
}
__device__ __forceinline__ uint32_t redux_min_u32(uint32_t v) {
    uint32_t r;
    asm volatile("redux.sync.min.u32 %0, %1, 0xffffffff;" : "=r"(r) : "r"(v));
    return r;
}
#define MMA16816(d, a, b0_, b1_)                                                 \
    asm volatile("mma.sync.aligned.m16n8k16.row.col.f32.bf16.bf16.f32 "          \
                 "{%0,%1,%2,%3}, {%4,%5,%6,%7}, {%8,%9}, {%0,%1,%2,%3};"         \
                 : "+f"((d)[0]), "+f"((d)[1]), "+f"((d)[2]), "+f"((d)[3])        \
                 : "r"((a)[0]), "r"((a)[1]), "r"((a)[2]), "r"((a)[3]),           \
                   "r"(b0_), "r"(b1_))

#define MBARRIER_INIT(mbar, cnt) \
    asm volatile("mbarrier.init.shared.b64 [%0], %1;" \
                 :: "r"((uint32_t)(mbar)), "r"((uint32_t)(cnt)) : "memory")
#define MBARRIER_EXPECT_TX(mbar, tx) \
    asm volatile("mbarrier.arrive.expect_tx.shared.b64 _, [%0], %1;" \
                 :: "r"((uint32_t)(mbar)), "r"((uint32_t)(tx)) : "memory")
#define MBARRIER_WAIT_PARITY(mbar, parity) do {                                     \
    uint32_t _m = (uint32_t)(mbar); uint32_t _p = (uint32_t)(parity);               \
    asm volatile("{\n .reg .pred P1;\n"                                             \
                 "WAIT_LOOP_%=:\n"                                                  \
                 " mbarrier.try_wait.parity.acquire.cta.shared::cta.b64 P1,[%0],%1,0x989680;\n" \
                 " @P1 bra.uni WAIT_DONE_%=;\n"                                     \
                 " bra.uni WAIT_LOOP_%=;\n"                                         \
                 "WAIT_DONE_%=:\n}"                                                 \
                 :: "r"(_m), "r"(_p) : "memory");                                   \
} while (0)
#define BULK_G2S(dst, src, bytes, mbar) \
    asm volatile("cp.async.bulk.shared::cta.global.mbarrier::complete_tx::bytes " \
                 "[%0], [%1], %2, [%3];" \
                 :: "r"((uint32_t)(dst)), "l"(src), "r"((uint32_t)(bytes)), \
                    "r"((uint32_t)(mbar)) : "memory")

__device__ __forceinline__ bool ltp(float av, int ai, float bv, int bi) {
    return (av < bv) || (av == bv && ai < bi);
}
__device__ __forceinline__ void ceu(uint32_t& a, uint32_t& b) {
    uint32_t mn = min(a, b);
    b = max(a, b);
    a = mn;
}
__device__ __forceinline__ void sort4u(uint32_t (&k)[4]) {
    ceu(k[0], k[1]); ceu(k[2], k[3]);
    ceu(k[0], k[2]); ceu(k[1], k[3]);
    ceu(k[1], k[2]);
}
__device__ __forceinline__ float predict(float m1, float m2) {
    float d1 = sqrtf(fmaxf(m1, 0.f) + EPSQ);
    float d2 = sqrtf(fmaxf(m2, 0.f) + EPSQ);
    float e  = expf(d1);
    return (d1 / d2 < TLC) ? 2.f / (1.f + e) : 2.f / (1.f + LC * e);
}

// ---------------------------------------------------------------------------
// Kernel 1: fused bf16 convert (to swizzled chunk layout) + fp32 row norms.
// ---------------------------------------------------------------------------
__global__ void convert_norms_kernel(const float* __restrict__ x) {
    if (blockIdx.x == 0 && threadIdx.x == 0) g_flagcnt = 0;
    int warp = (blockIdx.x * blockDim.x + threadIdx.x) >> 5;  // 0..8191
    int lane = threadIdx.x & 31;
    int gw0 = warp * 2;                                       // global rows
    const float* xr0 = x + (size_t)gw0 * CDIM + lane * 8;
    const float* xr1 = xr0 + CDIM;
    float4 a0 = *(const float4*)xr0;
    float4 a1 = *(const float4*)(xr0 + 4);
    float4 b0 = *(const float4*)xr1;
    float4 b1 = *(const float4*)(xr1 + 4);

    float sa = a0.x*a0.x + a0.y*a0.y + a0.z*a0.z + a0.w*a0.w
             + a1.x*a1.x + a1.y*a1.y + a1.z*a1.z + a1.w*a1.w;
    float sb = b0.x*b0.x + b0.y*b0.y + b0.z*b0.z + b0.w*b0.w
             + b1.x*b1.x + b1.y*b1.y + b1.z*b1.z + b1.w*b1.w;

    const int kc = lane >> 3, gg = lane & 7;
    char* xh = (char*)g_xhi;
    auto chunk_off = [&](int gw) -> size_t {
        int r = gw & 127;
        return (size_t)(((gw >> 7) * 4) + kc) * CHB
             + (size_t)(r * 128 + (((gg ^ (r & 7))) << 4));
    };

    __nv_bfloat162 p0(__float2bfloat16(a0.x), __float2bfloat16(a0.y));
    __nv_bfloat162 p1(__float2bfloat16(a0.z), __float2bfloat16(a0.w));
    __nv_bfloat162 p2(__float2bfloat16(a1.x), __float2bfloat16(a1.y));
    __nv_bfloat162 p3(__float2bfloat16(a1.z), __float2bfloat16(a1.w));
    uint4 u;
    u.x = *(uint32_t*)&p0; u.y = *(uint32_t*)&p1;
    u.z = *(uint32_t*)&p2; u.w = *(uint32_t*)&p3;
    *(uint4*)(xh + chunk_off(gw0)) = u;
    __nv_bfloat162 q0(__float2bfloat16(b0.x), __float2bfloat16(b0.y));
    __nv_bfloat162 q1(__float2bfloat16(b0.z), __float2bfloat16(b0.w));
    __nv_bfloat162 q2(__float2bfloat16(b1.x), __float2bfloat16(b1.y));
    __nv_bfloat162 q3(__float2bfloat16(b1.z), __float2bfloat16(b1.w));
    u.x = *(uint32_t*)&q0; u.y = *(uint32_t*)&q1;
    u.z = *(uint32_t*)&q2; u.w = *(uint32_t*)&q3;
    *(uint4*)(xh + chunk_off(gw0 + 1)) = u;

    #pragma unroll
    for (int o = 16; o; o >>= 1) {
        sa += __shfl_xor_sync(0xffffffffu, sa, o);
        sb += __shfl_xor_sync(0xffffffffu, sb, o);
    }
    if (lane == 0) { g_norms[gw0] = sa; g_norms[gw0 + 1] = sb; }
}

// ---------------------------------------------------------------------------
// Kernel 2: single-pass bf16 Gram tile-pair, bulk-async staging, packed
// dual-index keys with dual-orientation conflict-free swizzle, 2-task redux.
// ---------------------------------------------------------------------------
__global__ __launch_bounds__(512, 2)
void fcm_pair_kernel() {
    extern __shared__ __align__(128) char smem[];
    __shared__ __align__(8) unsigned long long s_mbar[2];
    const uint32_t sbase = smem_u32(smem);
    const uint32_t mb0 = smem_u32(&s_mbar[0]);
    const uint32_t mb1 = smem_u32(&s_mbar[1]);

    const int tid  = threadIdx.x;
    const int lane = tid & 31;
    const int w    = tid >> 5;
    const int mw   = w >> 2;
    const int nw   = w & 3;
    const int b    = blockIdx.y;

    int p = blockIdx.x;
    int i = (int)((65.0f - sqrtf(4225.0f - 8.0f * (float)p)) * 0.5f);
    while ((i + 1) * (65 - (i + 1)) / 2 <= p) ++i;
    while (i * (65 - i) / 2 > p) --i;
    const int j = i + (p - i * (65 - i) / 2);
    const int row0 = i * 128, col0 = j * 128;
    const bool diag = (i == j);

    const char* xch = (const char*)g_xhi + (size_t)b * (NSTRIP * 4) * CHB;
    const int lrow = ((lane >> 3) & 1) * 8 + (lane & 7);
    const int hi16 = lane >> 4;

    if (tid == 0) { MBARRIER_INIT(mb0, 1); MBARRIER_INIT(mb1, 1); }
    __syncthreads();

    auto stage = [&](int kc) {    // tid==0 only
        const int buf = kc & 1;
        const uint32_t mb = buf ? mb1 : mb0;
        const uint32_t dst = sbase + (uint32_t)(buf * BUFB);
        MBARRIER_EXPECT_TX(mb, diag ? CHB : 2 * CHB);
        BULK_G2S(dst, xch + (size_t)(i * 4 + kc) * CHB, CHB, mb);
        if (!diag)
            BULK_G2S(dst + CHB, xch + (size_t)(j * 4 + kc) * CHB, CHB, mb);
    };
    if (tid == 0) stage(0);

    float acc[2][4][4];
    #pragma unroll
    for (int mf = 0; mf < 2; ++mf)
        #pragma unroll
        for (int nf = 0; nf < 4; ++nf)
            #pragma unroll
            for (int e = 0; e < 4; ++e) acc[mf][nf][e] = 0.f;

    int ph0 = 0, ph1 = 0;
    for (int kc = 0; kc < 4; ++kc) {
        if (kc & 1) { MBARRIER_WAIT_PARITY(mb1, ph1); ph1 ^= 1; }
        else        { MBARRIER_WAIT_PARITY(mb0, ph0); ph0 ^= 1; }
        __syncthreads();                  // all warps past prior chunk's ldsm
        if (kc < 3 && tid == 0) stage(kc + 1);

        const uint32_t abase = sbase + (uint32_t)((kc & 1) * BUFB);
        const uint32_t bbase = diag ? abase : abase + CHB;
        const int ra = mw * 32 + lrow;
        const int rb = nw * 32 + lrow;
        const uint32_t am = (uint32_t)(lrow & 7);
        #pragma unroll
        for (int ks = 0; ks < 4; ++ks) {
            const uint32_t goff = (((uint32_t)(ks * 2 + hi16) ^ am) << 4);
            uint32_t ah[2][4], bh[2][4];
            ldsm_x4(ah[0], abase + (uint32_t)(ra * 128) + goff);
            ldsm_x4(ah[1], abase + (uint32_t)((ra + 16) * 128) + goff);
            ldsm_x4(bh[0], bbase + (uint32_t)(rb * 128) + goff);
            ldsm_x4(bh[1], bbase + (uint32_t)((rb + 16) * 128) + goff);
            #pragma unroll
            for (int mf = 0; mf < 2; ++mf)
                #pragma unroll
                for (int nf = 0; nf < 4; ++nf)
                    MMA16816(acc[mf][nf], ah[mf],
                             bh[nf >> 1][nf & 1], bh[nf >> 1][(nf & 1) + 2]);
        }
    }
    __syncthreads();                 // ldsm done; alias smem as key D-tile

    // ---- packed dual-index keys into dual-orientation swizzled SMEM ----
    // word(r,c) = r*128 + ((c>>2 ^ (r&31))<<2) + ((c&3) ^ ((r>>3)&3))
    uint32_t* Dt = (uint32_t*)smem;
    #pragma unroll
    for (int mf = 0; mf < 2; ++mf) {
        const int r0l = mw * 32 + mf * 16 + (lane >> 2);
        const int r1l = r0l + 8;
        const float na0 = g_norms[b * HW + row0 + r0l];
        const float na1 = g_norms[b * HW + row0 + r1l];
        const float* nbp = g_norms + b * HW + col0 + nw * 32 + (lane & 3) * 2;
        const int v0 = (r0l >> 3) & 3;
        const int v1 = (r1l >> 3) & 3;      // = v0 ^ 1
        #pragma unroll
        for (int nf = 0; nf < 4; ++nf) {
            float2 nb = *(const float2*)(nbp + nf * 8);
            const int cl = nw * 32 + nf * 8 + (lane & 3) * 2;
            const int cb = cl >> 2, cq = cl & 3;       // cq in {0,2}
            uint32_t k00 = (__float_as_uint(na0 + nb.x - 2.f * acc[mf][nf][0]) & VMASK)
                         | ((uint32_t)r0l << 7) | (uint32_t)cl;
            uint32_t k01 = (__float_as_uint(na0 + nb.y - 2.f * acc[mf][nf][1]) & VMASK)
                         | ((uint32_t)r0l << 7) | (uint32_t)(cl + 1);
            uint32_t k10 = (__float_as_uint(na1 + nb.x - 2.f * acc[mf][nf][2]) & VMASK)
                         | ((uint32_t)r1l << 7) | (uint32_t)cl;
            uint32_t k11 = (__float_as_uint(na1 + nb.y - 2.f * acc[mf][nf][3]) & VMASK)
                         | ((uint32_t)r1l << 7) | (uint32_t)(cl + 1);
            if (diag) {
                if (r0l == cl)     k00 = 0xFFFFFFFFu;
                if (r0l == cl + 1) k01 = 0xFFFFFFFFu;
                if (r1l == cl)     k10 = 0xFFFFFFFFu;
                if (r1l == cl + 1) k11 = 0xFFFFFFFFu;
            }
            const int base0 = r0l * DPW + ((cb ^ (r0l & 31)) << 2) + (cq ^ (v0 & 2));
            const int base1 = r1l * DPW + ((cb ^ (r1l & 31)) << 2) + (cq ^ (v1 & 2));
            *(uint2*)&Dt[base0] = (v0 & 1) ? make_uint2(k01, k00)
                                           : make_uint2(k00, k01);
            *(uint2*)&Dt[base1] = (v1 & 1) ? make_uint2(k11, k10)
                                           : make_uint2(k10, k11);
        }
    }
    __syncthreads();

    // ---- top-4 extraction: 2 tasks/iter, pure load+sort+pop ----
    const uint32_t vlo = (uint32_t)((lane >> 3) & 3);   // col-task low-bit xor
    const int ntask = diag ? 128 : 256;
    for (int t0 = w; t0 < ntask; t0 += 32) {
        uint32_t k[2][4];
        bool isrow[2];
        #pragma unroll
        for (int u = 0; u < 2; ++u) {
            const int t = t0 + 16 * u;
            isrow[u] = (t < 128);
            if (isrow[u]) {
                const int rr = t;
                const uint4 dv =
                    *(const uint4*)&Dt[rr * DPW + ((lane ^ (rr & 31)) << 2)];
                k[u][0] = dv.x; k[u][1] = dv.y; k[u][2] = dv.z; k[u][3] = dv.w;
            } else {
                const int cc = t - 128;
                const int cb = cc >> 2, cq = cc & 3;
                #pragma unroll
                for (int q = 0; q < 4; ++q) {
                    const int r = lane + 32 * q;
                    k[u][q] = Dt[r * DPW + (((cb ^ (r & 31)) << 2)
                                 | (cq ^ vlo))];
                }
            }
            sort4u(k[u]);
        }

        uint32_t myk[2];
        #pragma unroll
        for (int pp = 0; pp < 4; ++pp) {
            uint32_t g0 = redux_min_u32(k[0][0]);
            uint32_t g1 = redux_min_u32(k[1][0]);
            if (lane == pp) { myk[0] = g0; myk[1] = g1; }
            if (k[0][0] == g0) {
                k[0][0] = k[0][1]; k[0][1] = k[0][2];
                k[0][2] = k[0][3]; k[0][3] = 0xFFFFFFFFu;
            }
            if (k[1][0] == g1) {
                k[1][0] = k[1][1]; k[1][1] = k[1][2];
                k[1][2] = k[1][3]; k[1][3] = 0xFFFFFFFFu;
            }
        }
        if (lane < 4) {
            #pragma unroll
            for (int u = 0; u < 2; ++u) {
                const int t = t0 + 16 * u;
                const int grow = isrow[u] ? (row0 + t) : (col0 + (t - 128));
                const int slot = isrow[u] ? j : i;
                uint32_t kk = isrow[u] ? myk[u]
                    : ((myk[u] & VMASK) | ((myk[u] >> 7) & 0x7Fu));
                g_pc[(((size_t)(b * HW + grow)) * NSTRIP + slot) * 4 + lane] = kk;
            }
        }
    }
}

// ---------------------------------------------------------------------------
// Kernel 3: warp-per-row merge + exact fp32 refinement of 8 candidates.
// ---------------------------------------------------------------------------
__global__ void merge_refine_kernel(const float* __restrict__ x,
                                    float* __restrict__ out, int out_size) {
    int gw   = (blockIdx.x * blockDim.x + threadIdx.x) >> 5;
    int lane = threadIdx.x & 31;
    if (gw >= BATCH * HW) return;
    const int b = gw >> 12, rl = gw & 4095;

    const uint4 kk = *(const uint4*)(g_pc + ((size_t)gw * NSTRIP + lane) * 4);
    const uint32_t b1 = redux_min_u32(kk.w & VMASK);

    const uint32_t base = (uint32_t)lane * 128u;
    uint32_t mk[4];
    mk[0] = (kk.x & VMASK) | (base + (kk.x & 0x7Fu));
    mk[1] = (kk.y & VMASK) | (base + (kk.y & 0x7Fu));
    mk[2] = (kk.z & VMASK) | (base + (kk.z & 0x7Fu));
    mk[3] = (kk.w & VMASK) | (base + (kk.w & 0x7Fu));
    sort4u(mk);

    uint32_t gks[8];
    #pragma unroll
    for (int pp = 0; pp < 8; ++pp) {
        uint32_t gv = redux_min_u32(mk[0]);
        gks[pp] = gv;
        if (mk[0] == gv) {
            mk[0] = mk[1]; mk[1] = mk[2]; mk[2] = mk[3]; mk[3] = 0xFFFFFFFFu;
        }
    }

    const float* xb = x + (size_t)b * HW * CDIM;
    const float* xr = xb + (size_t)rl * CDIM + lane * 8;
    float4 a0 = *(const float4*)xr;
    float4 a1 = *(const float4*)(xr + 4);
    const float nr = g_norms[b * HW + rl];

    float s[8];
    #pragma unroll
    for (int k = 0; k < 8; ++k) {
        const int c = (int)(gks[k] & 0xFFFu);
        const float* xc = xb + (size_t)c * CDIM + lane * 8;
        float4 c0 = *(const float4*)xc;
        float4 c1 = *(const float4*)(xc + 4);
        s[k] = a0.x*c0.x + a0.y*c0.y + a0.z*c0.z + a0.w*c0.w
             + a1.x*c1.x + a1.y*c1.y + a1.z*c1.z + a1.w*c1.w;
    }
    #pragma unroll
    for (int off = 16; off; off >>= 1) {
        #pragma unroll
        for (int k = 0; k < 8; ++k)
            s[k] += __shfl_xor_sync(0xffffffffu, s[k], off);
    }

    float m1 = FLT_MAX, m2 = FLT_MAX; int j1 = 0, j2 = 0;
    #pragma unroll
    for (int k = 0; k < 8; ++k) {
        const int c = (int)(gks[k] & 0xFFFu);
        float D = nr + g_norms[b * HW + c] - 2.f * s[k];
        if (ltp(D, c, m1, j1)) { m2 = m1; j2 = j1; m1 = D; j1 = c; }
        else if (ltp(D, c, m2, j2)) { m2 = D; j2 = c; }
    }

    if (lane == 0) {
        out[(size_t)b * HW + rl] = predict(m1, m2);
        if (out_size >= 2 * BATCH * HW)
            out[(size_t)BATCH * HW + (size_t)b * HW + rl] = (float)j1;
        float bound = fminf(__uint_as_float(b1),
                            __uint_as_float(gks[7] & VMASK));
        if (m2 > bound - MARGIN) {
            int fi = atomicAdd(&g_flagcnt, 1);
            g_flaglist[fi] = gw;
        }
    }
}

// ---------------------------------------------------------------------------
// Kernel 4: exact full-row rescan for flagged rows (expected ~0 rows).
// ---------------------------------------------------------------------------
__global__ void fallback_kernel(const float* __restrict__ x,
                                float* __restrict__ out, int out_size) {
    __shared__ float sv1[256], sv2[256];
    __shared__ int   si1[256];
    const int n = g_flagcnt;
    for (int fi = blockIdx.x; fi < n; fi += gridDim.x) {
        const int rowg = g_flaglist[fi];
        const int b = rowg >> 12, r = rowg & 4095;
        const float* xb = x + (size_t)b * HW * CDIM;
        const float* xr = xb + (size_t)r * CDIM;
        const float  nr = g_norms[rowg];
        float v1 = FLT_MAX, v2 = FLT_MAX; int i1 = 0x7fffffff;
        for (int c = threadIdx.x; c < HW; c += 256) {
            if (c == r) continue;
            const float4* xc = (const float4*)(xb + (size_t)c * CDIM);
            float s = 0.f;
            #pragma unroll
            for (int d = 0; d < 64; ++d) {
                float4 va = ((const float4*)xr)[d];
                float4 vb = xc[d];
                s += va.x*vb.x + va.y*vb.y + va.z*vb.z + va.w*vb.w;
            }
            float D = nr + g_norms[b * HW + c] - 2.f * s;
            if (ltp(D, c, v1, i1)) { v2 = v1; v1 = D; i1 = c; }
            else if (D < v2) { v2 = D; }
        }
        sv1[threadIdx.x] = v1; sv2[threadIdx.x] = v2; si1[threadIdx.x] = i1;
        __syncthreads();
        for (int off = 128; off; off >>= 1) {
            if (threadIdx.x < off) {
                float b1 = sv1[threadIdx.x + off], b2 = sv2[threadIdx.x + off];
                int   bi = si1[threadIdx.x + off];
                float a1v = sv1[threadIdx.x]; int a1i = si1[threadIdx.x];
                if (ltp(b1, bi, a1v, a1i)) {
                    sv2[threadIdx.x] = fminf(a1v, b2);
                    sv1[threadIdx.x] = b1; si1[threadIdx.x] = bi;
                } else {
                    sv2[threadIdx.x] = fminf(sv2[threadIdx.x], b1);
                }
            }
            __syncthreads();
        }
        if (threadIdx.x == 0) {
            out[(size_t)b * HW + r] = predict(sv1[0], sv2[0]);
            if (out_size >= 2 * BATCH * HW)
                out[(size_t)BATCH * HW + (size_t)b * HW + r] = (float)si1[0];
        }
        __syncthreads();
    }
}

// ---------------------------------------------------------------------------
extern "C" void kernel_launch(void* const* d_in, const int* in_sizes, int n_in,
                              void* d_out, int out_size) {
    const float* x   = (const float*)d_in[0];
    float*       out = (float*)d_out;

    convert_norms_kernel<<<BATCH * HW / 16, 256>>>(x);

    cudaFuncSetAttribute(fcm_pair_kernel,
                         cudaFuncAttributeMaxDynamicSharedMemorySize, TOTSMEM);
    dim3 grid(NPAIR, BATCH);
    fcm_pair_kernel<<<grid, 512, TOTSMEM>>>();

    merge_refine_kernel<<<BATCH * HW / 8, 256>>>(x, out, out_size);
    fallback_kernel<<<64, 256>>>(x, out, out_size);
}